// round 9
// baseline (speedup 1.0000x reference)
#include <cuda_runtime.h>
#include <cuda_fp16.h>
#include <math.h>
#include <cstdint>

// Problem constants
#define Bsz 2
#define SQd 256
#define SKd 512
#define Ed  512
#define Hd  256

#define NQ (Bsz*SQd)   // 512
#define NK (Bsz*SKd)   // 1024
#define OFF_QF 0
#define OFF_KF (OFF_QF + NQ*Hd)
#define OFF_QP (OFF_KF + NK*Hd)
#define OFF_KP (OFF_QP + NQ*Hd)
#define OFF_QV (OFF_KP + NK*Hd)
#define OFF_KV (OFF_QV + NQ*Hd)
#define SCRATCH_FLOATS (OFF_KV + NK*Hd)

__device__ float g_scratch[SCRATCH_FLOATS];
// Transposed fp16 weights: [W1h][W2h], each [256 n][256 k]
__device__ __align__(16) __half g_wt[2 * 256 * 256];

__device__ __forceinline__ float frelu(float x) { return x > 0.f ? x : 0.f; }
__device__ __forceinline__ float4 ldg4(const float* p) { return __ldg((const float4*)p); }

__device__ __forceinline__ uint32_t smem_to_u32(const void* p) {
    uint32_t a;
    asm("{ .reg .u64 t; cvta.to.shared.u64 t, %1; cvt.u32.u64 %0, t; }" : "=r"(a) : "l"(p));
    return a;
}
__device__ __forceinline__ void cp16(uint32_t dst, const void* src) {
    asm volatile("cp.async.cg.shared.global [%0], [%1], 16;" :: "r"(dst), "l"(src));
}
#define CP_COMMIT() asm volatile("cp.async.commit_group;" ::: "memory")
#define CP_WAIT0()  asm volatile("cp.async.wait_group 0;" ::: "memory")

// fp16 inputs, fp32 accumulate
__device__ __forceinline__ void mma_f32acc(float* c, const uint32_t* a, const uint32_t* b) {
    asm volatile(
        "mma.sync.aligned.m16n8k16.row.col.f32.f16.f16.f32 "
        "{%0,%1,%2,%3}, {%4,%5,%6,%7}, {%8,%9}, {%0,%1,%2,%3};"
        : "+f"(c[0]), "+f"(c[1]), "+f"(c[2]), "+f"(c[3])
        : "r"(a[0]), "r"(a[1]), "r"(a[2]), "r"(a[3]), "r"(b[0]), "r"(b[1]));
}
__device__ __forceinline__ void ldsm4(uint32_t* r, uint32_t addr) {
    asm volatile("ldmatrix.sync.aligned.m8n8.x4.shared.b16 {%0,%1,%2,%3}, [%4];"
                 : "=r"(r[0]), "=r"(r[1]), "=r"(r[2]), "=r"(r[3]) : "r"(addr));
}

// fp16 hi/lo split of two fp32 values, packed
__device__ __forceinline__ void split2h(float x0, float x1, uint32_t& h, uint32_t& l) {
    __half h0 = __float2half_rn(x0), h1 = __float2half_rn(x1);
    float r0 = x0 - __half2float(h0), r1 = x1 - __half2float(h1);
    __half l0 = __float2half_rn(r0), l1 = __float2half_rn(r1);
    h = (uint32_t)__half_as_ushort(h0) | ((uint32_t)__half_as_ushort(h1) << 16);
    l = (uint32_t)__half_as_ushort(l0) | ((uint32_t)__half_as_ushort(l1) << 16);
}

// ---------------------------------------------------------------------------
// Prep GEMM tile: cp.async double-buffered. 256 threads, tile 32 x 64.
// ---------------------------------------------------------------------------
__device__ void gemm_tile(const float* __restrict__ A,
                          const float* __restrict__ W,
                          const float* __restrict__ bias,
                          float* __restrict__ C,
                          int K, int act, int row0, int col0)
{
    __shared__ float As[2][32 * 32];
    __shared__ float Ws[2][32 * 64];
    const int tid = threadIdx.x;
    const int tr  = tid >> 4;
    const int tc  = tid & 15;
    const uint32_t as0 = smem_to_u32(As);
    const uint32_t ws0 = smem_to_u32(Ws);

    const int lr  = tid >> 3;          // A loader: row 0..31
    const int lck = (tid & 7) * 4;     // A loader: col group

    // prefetch chunk 0
    cp16(as0 + (uint32_t)(lr * 32 + lck) * 4, A + (size_t)(row0 + lr) * K + lck);
    #pragma unroll
    for (int i = 0; i < 2; i++) {
        int f = tid + 256 * i; int k = f >> 4; int cc = (f & 15) * 4;
        cp16(ws0 + (uint32_t)(k * 64 + cc) * 4, W + (size_t)k * 256 + col0 + cc);
    }
    CP_COMMIT();

    float acc0x=0.f,acc0y=0.f,acc0z=0.f,acc0w=0.f,acc1x=0.f,acc1y=0.f,acc1z=0.f,acc1w=0.f;
    if (bias) {
        float4 bb = ldg4(bias + col0 + tc * 4);
        acc0x=bb.x;acc0y=bb.y;acc0z=bb.z;acc0w=bb.w;
        acc1x=bb.x;acc1y=bb.y;acc1z=bb.z;acc1w=bb.w;
    }

    const int nch = K >> 5;
    for (int g = 0; g < nch; g++) {
        CP_WAIT0();
        __syncthreads();
        if (g + 1 < nch) {
            int kc = (g + 1) * 32;
            uint32_t bsel = (uint32_t)((g + 1) & 1);
            cp16(as0 + bsel * 4096 + (uint32_t)(lr * 32 + lck) * 4,
                 A + (size_t)(row0 + lr) * K + kc + lck);
            #pragma unroll
            for (int i = 0; i < 2; i++) {
                int f = tid + 256 * i; int k = f >> 4; int cc = (f & 15) * 4;
                cp16(ws0 + bsel * 8192 + (uint32_t)(k * 64 + cc) * 4,
                     W + (size_t)(kc + k) * 256 + col0 + cc);
            }
            CP_COMMIT();
        }
        const float* Asb = As[g & 1];
        const float* Wsb = Ws[g & 1];
        #pragma unroll 8
        for (int k = 0; k < 32; k++) {
            float a0 = Asb[(tr * 2) * 32 + k];
            float a1 = Asb[(tr * 2 + 1) * 32 + k];
            float4 w = *(const float4*)(Wsb + k * 64 + tc * 4);
            acc0x = fmaf(a0, w.x, acc0x); acc0y = fmaf(a0, w.y, acc0y);
            acc0z = fmaf(a0, w.z, acc0z); acc0w = fmaf(a0, w.w, acc0w);
            acc1x = fmaf(a1, w.x, acc1x); acc1y = fmaf(a1, w.y, acc1y);
            acc1z = fmaf(a1, w.z, acc1z); acc1w = fmaf(a1, w.w, acc1w);
        }
    }
    if (act) {
        acc0x=frelu(acc0x);acc0y=frelu(acc0y);acc0z=frelu(acc0z);acc0w=frelu(acc0w);
        acc1x=frelu(acc1x);acc1y=frelu(acc1y);acc1z=frelu(acc1z);acc1w=frelu(acc1w);
    }
    *(float4*)(C + (size_t)(row0+tr*2)  *256 + col0 + tc*4) = make_float4(acc0x,acc0y,acc0z,acc0w);
    *(float4*)(C + (size_t)(row0+tr*2+1)*256 + col0 + tc*4) = make_float4(acc1x,acc1y,acc1z,acc1w);
}

// Launch 1: both encoders. grid (4, 48)
__global__ void encoder_kernel(const float* __restrict__ query,
                               const float* __restrict__ key_,
                               const float* __restrict__ Wqe, const float* __restrict__ bqe,
                               const float* __restrict__ Wke, const float* __restrict__ bke)
{
    float* S = g_scratch;
    int y = blockIdx.y;
    if (y < 16)
        gemm_tile(query, Wqe, bqe, S + OFF_QF, Ed, 1, y * 32, blockIdx.x * 64);
    else
        gemm_tile(key_,  Wke, bke, S + OFF_KF, Ed, 1, (y - 16) * 32, blockIdx.x * 64);
}

// Launch 2: 4 projections + weight transpose (fp16). grid (4, 32, 5)
__global__ void proj_trans_kernel(const float* __restrict__ W0,
                                  const float* __restrict__ Wv1,
                                  const float* __restrict__ W1,
                                  const float* __restrict__ W2)
{
    float* S = g_scratch;
    const int z = blockIdx.z;
    if (z < 4) {
        const float* A; const float* W; float* C;
        switch (z) {
            case 0: A = S + OFF_QF; W = W0;            C = S + OFF_QP; break;
            case 1: A = S + OFF_KF; W = W0 + Hd * Hd;  C = S + OFF_KP; break;
            case 2: A = S + OFF_QF; W = Wv1;           C = S + OFF_QV; break;
            default:A = S + OFF_KF; W = Wv1 + Hd * Hd; C = S + OFF_KV; break;
        }
        int M = (z == 1 || z == 3) ? 1024 : 512;
        if (blockIdx.y * 32 >= M) return;
        gemm_tile(A, W, nullptr, C, Hd, 0, blockIdx.y * 32, blockIdx.x * 64);
    } else {
        // transpose + fp16 round of W1, W2 into g_wt (Wt[n][k] row-major)
        int lin = blockIdx.y * 4 + blockIdx.x;      // 0..127
        const float* W = (lin >= 64) ? W2 : W1;
        __half* oh = g_wt + (size_t)(lin >= 64 ? 1 : 0) * 65536;
        int base = (lin & 63) * 1024;
        #pragma unroll
        for (int t = 0; t < 4; t++) {
            int e = base + t * 256 + threadIdx.x;
            int n = e >> 8, k = e & 255;
            oh[e] = __float2half_rn(__ldg(W + (size_t)k * 256 + n));
        }
    }
}

// ---------------------------------------------------------------------------
// HMMA fused pair kernel. CTA = (b, q, 128 k-pairs). M=128, N=256, K=256.
// 512 threads, 16 warps: 4 (M, 32 rows) x 4 (N, 64 cols).
// D = (Ah + Al) @ Wh, both terms in one fp32 accumulator.
// ---------------------------------------------------------------------------
#define APITCH 264                       // fp16 elems per A row (528 B)
#define SM_AH 0
#define SM_AL (128 * APITCH * 2)         // 67584
#define SM_W  (2 * 128 * APITCH * 2)     // 135168
#define WBUF_BYTES (256 * 40 * 2)        // 20480, pitch 80 B
#define SM_PART (SM_W + 2 * WBUF_BYTES)  // 176128
#define SMEM_TOTAL (SM_PART + 512 * 4)   // 178176

__global__ void __launch_bounds__(512, 1)
pair_mma_kernel(const float* __restrict__ b0, const float* __restrict__ b1,
                const float* __restrict__ b2,
                const float* __restrict__ Wf, const float* __restrict__ bf,
                const float* __restrict__ bv1, const float* __restrict__ Wv2,
                const float* __restrict__ bv2,
                float* __restrict__ out)
{
    extern __shared__ char smem[];
    const uint32_t sbase = smem_to_u32(smem);

    const int tid = threadIdx.x;
    const int w   = tid >> 5;
    const int wm  = w >> 2;            // 0..3 : M group (32 rows)
    const int wn  = w & 3;             // 0..3 : N group (64 cols)
    const int lt  = tid & 31;
    const int lrow = lt >> 2;          // 0..7
    const int lc2  = (lt & 3) * 2;     // 0,2,4,6

    // ldmatrix per-lane row offsets
    const uint32_t a_rowoff = (uint32_t)(wm * 32 + (lt & 15)) * (APITCH * 2)
                            + (uint32_t)((lt >> 4) * 8) * 2;
    const uint32_t b_rowoff = (uint32_t)(wn * 64 + (lt & 7) + ((lt >> 4) & 1) * 8) * 80
                            + (uint32_t)((lt >> 3) & 1) * 16;

    const int kb = blockIdx.x, q = blockIdx.y, b = blockIdx.z;
    const int qrow  = b * SQd + q;
    const int krow0 = b * SKd + kb * 128;

    const float* qp = g_scratch + OFF_QP + (size_t)qrow  * Hd;
    const float* kp = g_scratch + OFF_KP + (size_t)krow0 * Hd;
    const float* qv = g_scratch + OFF_QV + (size_t)qrow  * Hd;
    const float* kv = g_scratch + OFF_KV + (size_t)krow0 * Hd;

    // ---- prefetch W chunk 0 (layer 0) via cp.async
    {
        #pragma unroll
        for (int it = 0; it < 2; it++) {
            int u = tid + it * 512;             // 0..1023
            int n = u >> 2, j = u & 3;
            cp16(sbase + SM_W + n * 80 + j * 16, g_wt + n * 256 + j * 8);
        }
        CP_COMMIT();
    }

    // ---- variance branch: v = relu(qv+kv+bv1); softplus(v.Wv2 + bv2)
    {
        const int r = tid >> 2, part = tid & 3;   // 128 rows x 4 threads
        const int c0 = part * 64;
        const float* qvr = qv + c0;
        const float* kvr = kv + (size_t)r * Hd + c0;
        const float* bvr = bv1 + c0;
        const float* wvr = Wv2 + c0;
        float s = 0.f;
        #pragma unroll
        for (int i = 0; i < 16; i++) {
            float4 a = ldg4(qvr + i * 4);
            float4 c = ldg4(kvr + i * 4);
            float4 bb = ldg4(bvr + i * 4);
            float4 ww = ldg4(wvr + i * 4);
            s = fmaf(frelu(a.x + c.x + bb.x), ww.x, s);
            s = fmaf(frelu(a.y + c.y + bb.y), ww.y, s);
            s = fmaf(frelu(a.z + c.z + bb.z), ww.z, s);
            s = fmaf(frelu(a.w + c.w + bb.w), ww.w, s);
        }
        s += __shfl_xor_sync(0xffffffffu, s, 1);
        s += __shfl_xor_sync(0xffffffffu, s, 2);
        if (part == 0) {
            float x = s + __ldg(bv2);
            out[(size_t)Bsz * SQd * SKd + (size_t)qrow * SKd + kb * 128 + r] =
                fmaxf(x, 0.f) + log1pf(expf(-fabsf(x)));
        }
    }

    // ---- build A = relu(qp + kp + b0), fp16 hi/lo split -> SMEM
    {
        const int row = tid >> 2, part = tid & 3;
        const int c0 = part * 64;
        const float* qpr = qp + c0;
        const float* kpr = kp + (size_t)row * Hd + c0;
        const float* b0r = b0 + c0;
        #pragma unroll
        for (int j4 = 0; j4 < 16; j4++) {
            float4 a  = ldg4(qpr + j4 * 4);
            float4 c  = ldg4(kpr + j4 * 4);
            float4 bb = ldg4(b0r + j4 * 4);
            float x0 = frelu(a.x + c.x + bb.x);
            float x1 = frelu(a.y + c.y + bb.y);
            float x2 = frelu(a.z + c.z + bb.z);
            float x3 = frelu(a.w + c.w + bb.w);
            uint32_t h0, l0, h1, l1;
            split2h(x0, x1, h0, l0);
            split2h(x2, x3, h1, l1);
            uint32_t off = (uint32_t)row * (APITCH * 2) + (c0 + j4 * 4) * 2;
            *(uint2*)(smem + SM_AH + off) = make_uint2(h0, h1);
            *(uint2*)(smem + SM_AL + off) = make_uint2(l0, l1);
        }
    }
    CP_WAIT0();
    __syncthreads();

    // ---- accumulators: fp32 c[2][8][4]
    float c[2][8][4];
    #pragma unroll
    for (int mi = 0; mi < 2; mi++)
        #pragma unroll
        for (int ni = 0; ni < 8; ni++)
            #pragma unroll
            for (int jj = 0; jj < 4; jj++) c[mi][ni][jj] = 0.f;

    // ---- 16 chunks of K=32: layer = g>>3, kc = g&7; double-buffered cp.async
    #pragma unroll 1
    for (int g = 0; g < 16; g++) {
        const int kc = g & 7;
        const uint32_t wbufH = sbase + SM_W + (uint32_t)(g & 1) * WBUF_BYTES;

        // prefetch next chunk
        if (g + 1 < 16) {
            const __half* Wh = g_wt + (size_t)((g + 1) >> 3) * 65536;
            const int nkc = (g + 1) & 7;
            const uint32_t dbase = sbase + SM_W + ((g + 1) & 1) * WBUF_BYTES;
            #pragma unroll
            for (int it = 0; it < 2; it++) {
                int u = tid + it * 512;
                int n = u >> 2, j = u & 3;
                cp16(dbase + n * 80 + j * 16, Wh + n * 256 + nkc * 32 + j * 8);
            }
            CP_COMMIT();
        }

        // compute on current chunk: 2 k16 steps
        #pragma unroll
        for (int ks = 0; ks < 2; ks++) {
            const uint32_t a_k = (uint32_t)(kc * 32 + ks * 16) * 2;
            const uint32_t b_k = (uint32_t)ks * 32;

            uint32_t afh[2][4], afl[2][4], bh[8][2];
            #pragma unroll
            for (int mi = 0; mi < 2; mi++)
                ldsm4(afh[mi], sbase + SM_AH + a_rowoff + (uint32_t)mi * 16 * (APITCH * 2) + a_k);
            #pragma unroll
            for (int np = 0; np < 4; np++) {
                uint32_t r[4];
                ldsm4(r, wbufH + b_rowoff + (uint32_t)np * 16 * 80 + b_k);
                bh[2*np][0] = r[0]; bh[2*np][1] = r[1];
                bh[2*np+1][0] = r[2]; bh[2*np+1][1] = r[3];
            }
            // Ah @ Wh
            #pragma unroll
            for (int mi = 0; mi < 2; mi++)
                #pragma unroll
                for (int ni = 0; ni < 8; ni++)
                    mma_f32acc(c[mi][ni], afh[mi], bh[ni]);
            #pragma unroll
            for (int mi = 0; mi < 2; mi++)
                ldsm4(afl[mi], sbase + SM_AL + a_rowoff + (uint32_t)mi * 16 * (APITCH * 2) + a_k);
            // Al @ Wh (same accumulator)
            #pragma unroll
            for (int mi = 0; mi < 2; mi++)
                #pragma unroll
                for (int ni = 0; ni < 8; ni++)
                    mma_f32acc(c[mi][ni], afl[mi], bh[ni]);
        }

        CP_WAIT0();
        __syncthreads();

        // ---- between layers: h1 = relu(D + b1) -> split -> A SMEM; reset accum
        if (g == 7) {
            #pragma unroll
            for (int ni = 0; ni < 8; ni++) {
                int n = wn * 64 + ni * 8 + lc2;
                float2 bb = *(const float2*)(b1 + n);
                #pragma unroll
                for (int mi = 0; mi < 2; mi++) {
                    int m1 = wm * 32 + mi * 16 + lrow;
                    float x0 = frelu(c[mi][ni][0] + bb.x);
                    float x1 = frelu(c[mi][ni][1] + bb.y);
                    float y0 = frelu(c[mi][ni][2] + bb.x);
                    float y1 = frelu(c[mi][ni][3] + bb.y);
                    uint32_t h, l;
                    uint32_t off1 = (uint32_t)m1 * (APITCH * 2) + n * 2;
                    split2h(x0, x1, h, l);
                    *(uint32_t*)(smem + SM_AH + off1) = h;
                    *(uint32_t*)(smem + SM_AL + off1) = l;
                    uint32_t off2 = off1 + 8 * (APITCH * 2);
                    split2h(y0, y1, h, l);
                    *(uint32_t*)(smem + SM_AH + off2) = h;
                    *(uint32_t*)(smem + SM_AL + off2) = l;
                    c[mi][ni][0] = 0.f; c[mi][ni][1] = 0.f;
                    c[mi][ni][2] = 0.f; c[mi][ni][3] = 0.f;
                }
            }
            __syncthreads();
        }
    }

    // ---- final epilogue: logit = relu(D + b2) . Wf + bf
    float* part = (float*)(smem + SM_PART);
    float ps1[2], ps2[2];
    #pragma unroll
    for (int mi = 0; mi < 2; mi++) { ps1[mi] = 0.f; ps2[mi] = 0.f; }
    #pragma unroll
    for (int ni = 0; ni < 8; ni++) {
        int n = wn * 64 + ni * 8 + lc2;
        float2 bb = *(const float2*)(b2 + n);
        float2 wf = *(const float2*)(Wf + n);
        #pragma unroll
        for (int mi = 0; mi < 2; mi++) {
            ps1[mi] = fmaf(frelu(c[mi][ni][0] + bb.x), wf.x, ps1[mi]);
            ps1[mi] = fmaf(frelu(c[mi][ni][1] + bb.y), wf.y, ps1[mi]);
            ps2[mi] = fmaf(frelu(c[mi][ni][2] + bb.x), wf.x, ps2[mi]);
            ps2[mi] = fmaf(frelu(c[mi][ni][3] + bb.y), wf.y, ps2[mi]);
        }
    }
    #pragma unroll
    for (int mi = 0; mi < 2; mi++) {
        ps1[mi] += __shfl_xor_sync(0xffffffffu, ps1[mi], 1);
        ps1[mi] += __shfl_xor_sync(0xffffffffu, ps1[mi], 2);
        ps2[mi] += __shfl_xor_sync(0xffffffffu, ps2[mi], 1);
        ps2[mi] += __shfl_xor_sync(0xffffffffu, ps2[mi], 2);
    }
    if ((lt & 3) == 0) {
        #pragma unroll
        for (int mi = 0; mi < 2; mi++) {
            int m1 = wm * 32 + mi * 16 + lrow;
            part[wn * 128 + m1]     = ps1[mi];
            part[wn * 128 + m1 + 8] = ps2[mi];
        }
    }
    __syncthreads();
    if (tid < 128) {
        float s = part[tid] + part[128 + tid] + part[256 + tid] + part[384 + tid]
                + __ldg(bf);
        out[(size_t)qrow * SKd + kb * 128 + tid] = s;
    }
}

// ---------------------------------------------------------------------------
// Launch (3 launches per call)
// ---------------------------------------------------------------------------
extern "C" void kernel_launch(void* const* d_in, const int* in_sizes, int n_in,
                              void* d_out, int out_size)
{
    (void)in_sizes; (void)n_in; (void)out_size;
    const float* query = (const float*)d_in[0];
    const float* key_  = (const float*)d_in[1];
    const float* Wqe   = (const float*)d_in[2];
    const float* bqe   = (const float*)d_in[3];
    const float* Wke   = (const float*)d_in[4];
    const float* bke   = (const float*)d_in[5];
    const float* W0    = (const float*)d_in[6];
    const float* b0    = (const float*)d_in[7];
    const float* W1    = (const float*)d_in[8];
    const float* b1    = (const float*)d_in[9];
    const float* W2    = (const float*)d_in[10];
    const float* b2    = (const float*)d_in[11];
    const float* Wf    = (const float*)d_in[12];
    const float* bf    = (const float*)d_in[13];
    const float* Wv1   = (const float*)d_in[14];
    const float* bv1   = (const float*)d_in[15];
    const float* Wv2   = (const float*)d_in[16];
    const float* bv2   = (const float*)d_in[17];
    float* out = (float*)d_out;

    cudaFuncSetAttribute(pair_mma_kernel,
                         cudaFuncAttributeMaxDynamicSharedMemorySize, SMEM_TOTAL);

    // 1: encoders (qf, kf)
    encoder_kernel<<<dim3(4, 48), 256>>>(query, key_, Wqe, bqe, Wke, bke);
    // 2: projections (qp,kp,qv,kv) + W1/W2 transpose (fp16)
    proj_trans_kernel<<<dim3(4, 32, 5), 256>>>(W0, Wv1, W1, W2);
    // 3: fused HMMA pair MLP (2-term split, 512 threads)
    pair_mma_kernel<<<dim3(SKd / 128, SQd, Bsz), 512, SMEM_TOTAL>>>(
        b0, b1, b2, Wf, bf, bv1, Wv2, bv2, out);
}

// round 10
// speedup vs baseline: 1.0959x; 1.0959x over previous
#include <cuda_runtime.h>
#include <cuda_fp16.h>
#include <math.h>
#include <cstdint>

// Problem constants
#define Bsz 2
#define SQd 256
#define SKd 512
#define Ed  512
#define Hd  256

#define NQ (Bsz*SQd)   // 512
#define NK (Bsz*SKd)   // 1024
#define OFF_QF 0
#define OFF_KF (OFF_QF + NQ*Hd)
#define OFF_QP (OFF_KF + NK*Hd)
#define OFF_KP (OFF_QP + NQ*Hd)
#define OFF_QV (OFF_KP + NK*Hd)
#define OFF_KV (OFF_QV + NQ*Hd)
#define SCRATCH_FLOATS (OFF_KV + NK*Hd)

__device__ float g_scratch[SCRATCH_FLOATS];
// Transposed fp16 weights: [W1h][W2h], each [256 n][256 k]
__device__ __align__(16) __half g_wt[2 * 256 * 256];

__device__ __forceinline__ float frelu(float x) { return x > 0.f ? x : 0.f; }
__device__ __forceinline__ float4 ldg4(const float* p) { return __ldg((const float4*)p); }

__device__ __forceinline__ uint32_t smem_to_u32(const void* p) {
    uint32_t a;
    asm("{ .reg .u64 t; cvta.to.shared.u64 t, %1; cvt.u32.u64 %0, t; }" : "=r"(a) : "l"(p));
    return a;
}
__device__ __forceinline__ void cp16(uint32_t dst, const void* src) {
    asm volatile("cp.async.cg.shared.global [%0], [%1], 16;" :: "r"(dst), "l"(src));
}
#define CP_COMMIT() asm volatile("cp.async.commit_group;" ::: "memory")
#define CP_WAIT0()  asm volatile("cp.async.wait_group 0;" ::: "memory")

// fp16 inputs, fp32 accumulate
__device__ __forceinline__ void mma_f32acc(float* c, const uint32_t* a, const uint32_t* b) {
    asm volatile(
        "mma.sync.aligned.m16n8k16.row.col.f32.f16.f16.f32 "
        "{%0,%1,%2,%3}, {%4,%5,%6,%7}, {%8,%9}, {%0,%1,%2,%3};"
        : "+f"(c[0]), "+f"(c[1]), "+f"(c[2]), "+f"(c[3])
        : "r"(a[0]), "r"(a[1]), "r"(a[2]), "r"(a[3]), "r"(b[0]), "r"(b[1]));
}
__device__ __forceinline__ void ldsm4(uint32_t* r, uint32_t addr) {
    asm volatile("ldmatrix.sync.aligned.m8n8.x4.shared.b16 {%0,%1,%2,%3}, [%4];"
                 : "=r"(r[0]), "=r"(r[1]), "=r"(r[2]), "=r"(r[3]) : "r"(addr));
}

// fp16 hi/lo split of two fp32 values, packed
__device__ __forceinline__ void split2h(float x0, float x1, uint32_t& h, uint32_t& l) {
    __half h0 = __float2half_rn(x0), h1 = __float2half_rn(x1);
    float r0 = x0 - __half2float(h0), r1 = x1 - __half2float(h1);
    __half l0 = __float2half_rn(r0), l1 = __float2half_rn(r1);
    h = (uint32_t)__half_as_ushort(h0) | ((uint32_t)__half_as_ushort(h1) << 16);
    l = (uint32_t)__half_as_ushort(l0) | ((uint32_t)__half_as_ushort(l1) << 16);
}

// ---------------------------------------------------------------------------
// Prep GEMM tile: cp.async double-buffered (verified R9). 256 threads, 32x64.
// ---------------------------------------------------------------------------
__device__ void gemm_tile(const float* __restrict__ A,
                          const float* __restrict__ W,
                          const float* __restrict__ bias,
                          float* __restrict__ C,
                          int K, int act, int row0, int col0)
{
    __shared__ float As[2][32 * 32];
    __shared__ float Ws[2][32 * 64];
    const int tid = threadIdx.x;
    const int tr  = tid >> 4;
    const int tc  = tid & 15;
    const uint32_t as0 = smem_to_u32(As);
    const uint32_t ws0 = smem_to_u32(Ws);

    const int lr  = tid >> 3;          // A loader: row 0..31
    const int lck = (tid & 7) * 4;     // A loader: col group

    // prefetch chunk 0
    cp16(as0 + (uint32_t)(lr * 32 + lck) * 4, A + (size_t)(row0 + lr) * K + lck);
    #pragma unroll
    for (int i = 0; i < 2; i++) {
        int f = tid + 256 * i; int k = f >> 4; int cc = (f & 15) * 4;
        cp16(ws0 + (uint32_t)(k * 64 + cc) * 4, W + (size_t)k * 256 + col0 + cc);
    }
    CP_COMMIT();

    float acc0x=0.f,acc0y=0.f,acc0z=0.f,acc0w=0.f,acc1x=0.f,acc1y=0.f,acc1z=0.f,acc1w=0.f;
    if (bias) {
        float4 bb = ldg4(bias + col0 + tc * 4);
        acc0x=bb.x;acc0y=bb.y;acc0z=bb.z;acc0w=bb.w;
        acc1x=bb.x;acc1y=bb.y;acc1z=bb.z;acc1w=bb.w;
    }

    const int nch = K >> 5;
    for (int g = 0; g < nch; g++) {
        CP_WAIT0();
        __syncthreads();
        if (g + 1 < nch) {
            int kc = (g + 1) * 32;
            uint32_t bsel = (uint32_t)((g + 1) & 1);
            cp16(as0 + bsel * 4096 + (uint32_t)(lr * 32 + lck) * 4,
                 A + (size_t)(row0 + lr) * K + kc + lck);
            #pragma unroll
            for (int i = 0; i < 2; i++) {
                int f = tid + 256 * i; int k = f >> 4; int cc = (f & 15) * 4;
                cp16(ws0 + bsel * 8192 + (uint32_t)(k * 64 + cc) * 4,
                     W + (size_t)(kc + k) * 256 + col0 + cc);
            }
            CP_COMMIT();
        }
        const float* Asb = As[g & 1];
        const float* Wsb = Ws[g & 1];
        #pragma unroll 8
        for (int k = 0; k < 32; k++) {
            float a0 = Asb[(tr * 2) * 32 + k];
            float a1 = Asb[(tr * 2 + 1) * 32 + k];
            float4 w = *(const float4*)(Wsb + k * 64 + tc * 4);
            acc0x = fmaf(a0, w.x, acc0x); acc0y = fmaf(a0, w.y, acc0y);
            acc0z = fmaf(a0, w.z, acc0z); acc0w = fmaf(a0, w.w, acc0w);
            acc1x = fmaf(a1, w.x, acc1x); acc1y = fmaf(a1, w.y, acc1y);
            acc1z = fmaf(a1, w.z, acc1z); acc1w = fmaf(a1, w.w, acc1w);
        }
    }
    if (act) {
        acc0x=frelu(acc0x);acc0y=frelu(acc0y);acc0z=frelu(acc0z);acc0w=frelu(acc0w);
        acc1x=frelu(acc1x);acc1y=frelu(acc1y);acc1z=frelu(acc1z);acc1w=frelu(acc1w);
    }
    *(float4*)(C + (size_t)(row0+tr*2)  *256 + col0 + tc*4) = make_float4(acc0x,acc0y,acc0z,acc0w);
    *(float4*)(C + (size_t)(row0+tr*2+1)*256 + col0 + tc*4) = make_float4(acc1x,acc1y,acc1z,acc1w);
}

// Launch 1: both encoders. grid (4, 48)
__global__ void encoder_kernel(const float* __restrict__ query,
                               const float* __restrict__ key_,
                               const float* __restrict__ Wqe, const float* __restrict__ bqe,
                               const float* __restrict__ Wke, const float* __restrict__ bke)
{
    float* S = g_scratch;
    int y = blockIdx.y;
    if (y < 16)
        gemm_tile(query, Wqe, bqe, S + OFF_QF, Ed, 1, y * 32, blockIdx.x * 64);
    else
        gemm_tile(key_,  Wke, bke, S + OFF_KF, Ed, 1, (y - 16) * 32, blockIdx.x * 64);
}

// Launch 2: 4 projections + weight transpose (fp16). grid (4, 32, 5)
__global__ void proj_trans_kernel(const float* __restrict__ W0,
                                  const float* __restrict__ Wv1,
                                  const float* __restrict__ W1,
                                  const float* __restrict__ W2)
{
    float* S = g_scratch;
    const int z = blockIdx.z;
    if (z < 4) {
        const float* A; const float* W; float* C;
        switch (z) {
            case 0: A = S + OFF_QF; W = W0;            C = S + OFF_QP; break;
            case 1: A = S + OFF_KF; W = W0 + Hd * Hd;  C = S + OFF_KP; break;
            case 2: A = S + OFF_QF; W = Wv1;           C = S + OFF_QV; break;
            default:A = S + OFF_KF; W = Wv1 + Hd * Hd; C = S + OFF_KV; break;
        }
        int M = (z == 1 || z == 3) ? 1024 : 512;
        if (blockIdx.y * 32 >= M) return;
        gemm_tile(A, W, nullptr, C, Hd, 0, blockIdx.y * 32, blockIdx.x * 64);
    } else {
        // transpose + fp16 round of W1, W2 into g_wt (Wt[n][k] row-major)
        int lin = blockIdx.y * 4 + blockIdx.x;      // 0..127
        const float* W = (lin >= 64) ? W2 : W1;
        __half* oh = g_wt + (size_t)(lin >= 64 ? 1 : 0) * 65536;
        int base = (lin & 63) * 1024;
        #pragma unroll
        for (int t = 0; t < 4; t++) {
            int e = base + t * 256 + threadIdx.x;
            int n = e >> 8, k = e & 255;
            oh[e] = __float2half_rn(__ldg(W + (size_t)k * 256 + n));
        }
    }
}

// ---------------------------------------------------------------------------
// HMMA fused pair kernel (R8 config: 256 threads, 8 warps 2Mx4N).
// CTA = (b, q, 128 k-pairs). M=128, N=256, K=256.
// D = (Ah + Al) @ Wh, both terms in one fp32 accumulator.
// ---------------------------------------------------------------------------
#define APITCH 264                       // fp16 elems per A row (528 B)
#define SM_AH 0
#define SM_AL (128 * APITCH * 2)         // 67584
#define SM_W  (2 * 128 * APITCH * 2)     // 135168
#define WBUF_BYTES (256 * 40 * 2)        // 20480, pitch 80 B
#define SM_PART (SM_W + 2 * WBUF_BYTES)  // 176128
#define SMEM_TOTAL (SM_PART + 512 * 4)   // 178176

__global__ void __launch_bounds__(256, 1)
pair_mma_kernel(const float* __restrict__ b0, const float* __restrict__ b1,
                const float* __restrict__ b2,
                const float* __restrict__ Wf, const float* __restrict__ bf,
                const float* __restrict__ bv1, const float* __restrict__ Wv2,
                const float* __restrict__ bv2,
                float* __restrict__ out)
{
    extern __shared__ char smem[];
    const uint32_t sbase = smem_to_u32(smem);

    const int tid = threadIdx.x;
    const int w   = tid >> 5;
    const int wm  = w >> 2;            // 0..1 : M group (64 rows)
    const int wn  = w & 3;             // 0..3 : N group (64 cols)
    const int lt  = tid & 31;
    const int lrow = lt >> 2;          // 0..7
    const int lc2  = (lt & 3) * 2;     // 0,2,4,6

    // ldmatrix per-lane row offsets
    const uint32_t a_rowoff = (uint32_t)(wm * 64 + (lt & 15)) * (APITCH * 2)
                            + (uint32_t)((lt >> 4) * 8) * 2;
    const uint32_t b_rowoff = (uint32_t)(wn * 64 + (lt & 7) + ((lt >> 4) & 1) * 8) * 80
                            + (uint32_t)((lt >> 3) & 1) * 16;

    const int kb = blockIdx.x, q = blockIdx.y, b = blockIdx.z;
    const int qrow  = b * SQd + q;
    const int krow0 = b * SKd + kb * 128;

    const float* qp = g_scratch + OFF_QP + (size_t)qrow  * Hd;
    const float* kp = g_scratch + OFF_KP + (size_t)krow0 * Hd;
    const float* qv = g_scratch + OFF_QV + (size_t)qrow  * Hd;
    const float* kv = g_scratch + OFF_KV + (size_t)krow0 * Hd;

    // ---- prefetch W chunk 0 (layer 0) via cp.async
    {
        #pragma unroll
        for (int it = 0; it < 4; it++) {
            int u = tid + it * 256;             // 0..1023
            int n = u >> 2, j = u & 3;
            cp16(sbase + SM_W + n * 80 + j * 16, g_wt + n * 256 + j * 8);
        }
        CP_COMMIT();
    }

    // ---- variance branch: v = relu(qv+kv+bv1); softplus(v.Wv2 + bv2)
    {
        const int r = tid >> 1, part = tid & 1;
        const float* qvr = qv + part * 128;
        const float* kvr = kv + (size_t)r * Hd + part * 128;
        const float* bvr = bv1 + part * 128;
        const float* wvr = Wv2 + part * 128;
        float s = 0.f;
        #pragma unroll
        for (int i = 0; i < 32; i++) {
            float4 a = ldg4(qvr + i * 4);
            float4 c = ldg4(kvr + i * 4);
            float4 bb = ldg4(bvr + i * 4);
            float4 ww = ldg4(wvr + i * 4);
            s = fmaf(frelu(a.x + c.x + bb.x), ww.x, s);
            s = fmaf(frelu(a.y + c.y + bb.y), ww.y, s);
            s = fmaf(frelu(a.z + c.z + bb.z), ww.z, s);
            s = fmaf(frelu(a.w + c.w + bb.w), ww.w, s);
        }
        s += __shfl_down_sync(0xffffffffu, s, 1);
        if (part == 0) {
            float x = s + __ldg(bv2);
            out[(size_t)Bsz * SQd * SKd + (size_t)qrow * SKd + kb * 128 + r] =
                fmaxf(x, 0.f) + log1pf(expf(-fabsf(x)));
        }
    }

    // ---- build A = relu(qp + kp + b0), fp16 hi/lo split -> SMEM
    {
        const int row = tid >> 1, half = (tid & 1) * 128;
        const float* qpr = qp + half;
        const float* kpr = kp + (size_t)row * Hd + half;
        const float* b0r = b0 + half;
        #pragma unroll
        for (int j4 = 0; j4 < 32; j4++) {
            float4 a  = ldg4(qpr + j4 * 4);
            float4 c  = ldg4(kpr + j4 * 4);
            float4 bb = ldg4(b0r + j4 * 4);
            float x0 = frelu(a.x + c.x + bb.x);
            float x1 = frelu(a.y + c.y + bb.y);
            float x2 = frelu(a.z + c.z + bb.z);
            float x3 = frelu(a.w + c.w + bb.w);
            uint32_t h0, l0, h1, l1;
            split2h(x0, x1, h0, l0);
            split2h(x2, x3, h1, l1);
            uint32_t off = (uint32_t)row * (APITCH * 2) + (half + j4 * 4) * 2;
            *(uint2*)(smem + SM_AH + off) = make_uint2(h0, h1);
            *(uint2*)(smem + SM_AL + off) = make_uint2(l0, l1);
        }
    }
    CP_WAIT0();
    __syncthreads();

    // ---- accumulators: fp32 c[4][8][4]
    float c[4][8][4];
    #pragma unroll
    for (int mi = 0; mi < 4; mi++)
        #pragma unroll
        for (int ni = 0; ni < 8; ni++)
            #pragma unroll
            for (int jj = 0; jj < 4; jj++) c[mi][ni][jj] = 0.f;

    // ---- 16 chunks of K=32: layer = g>>3, kc = g&7; double-buffered cp.async
    #pragma unroll 1
    for (int g = 0; g < 16; g++) {
        const int kc = g & 7;
        const uint32_t wbufH = sbase + SM_W + (uint32_t)(g & 1) * WBUF_BYTES;

        // prefetch next chunk
        if (g + 1 < 16) {
            const __half* Wh = g_wt + (size_t)((g + 1) >> 3) * 65536;
            const int nkc = (g + 1) & 7;
            const uint32_t dbase = sbase + SM_W + ((g + 1) & 1) * WBUF_BYTES;
            #pragma unroll
            for (int it = 0; it < 4; it++) {
                int u = tid + it * 256;
                int n = u >> 2, j = u & 3;
                cp16(dbase + n * 80 + j * 16, Wh + n * 256 + nkc * 32 + j * 8);
            }
            CP_COMMIT();
        }

        // compute on current chunk: 2 k16 steps
        #pragma unroll
        for (int ks = 0; ks < 2; ks++) {
            const uint32_t a_k = (uint32_t)(kc * 32 + ks * 16) * 2;
            const uint32_t b_k = (uint32_t)ks * 32;

            uint32_t afh[4][4], afl[4][4], bh[8][2];
            #pragma unroll
            for (int mi = 0; mi < 4; mi++)
                ldsm4(afh[mi], sbase + SM_AH + a_rowoff + (uint32_t)mi * 16 * (APITCH * 2) + a_k);
            #pragma unroll
            for (int np = 0; np < 4; np++) {
                uint32_t r[4];
                ldsm4(r, wbufH + b_rowoff + (uint32_t)np * 16 * 80 + b_k);
                bh[2*np][0] = r[0]; bh[2*np][1] = r[1];
                bh[2*np+1][0] = r[2]; bh[2*np+1][1] = r[3];
            }
            // Ah @ Wh
            #pragma unroll
            for (int mi = 0; mi < 4; mi++)
                #pragma unroll
                for (int ni = 0; ni < 8; ni++)
                    mma_f32acc(c[mi][ni], afh[mi], bh[ni]);
            #pragma unroll
            for (int mi = 0; mi < 4; mi++)
                ldsm4(afl[mi], sbase + SM_AL + a_rowoff + (uint32_t)mi * 16 * (APITCH * 2) + a_k);
            // Al @ Wh (same accumulator)
            #pragma unroll
            for (int mi = 0; mi < 4; mi++)
                #pragma unroll
                for (int ni = 0; ni < 8; ni++)
                    mma_f32acc(c[mi][ni], afl[mi], bh[ni]);
        }

        CP_WAIT0();
        __syncthreads();

        // ---- between layers: h1 = relu(D + b1) -> split -> A SMEM; reset accum
        if (g == 7) {
            #pragma unroll
            for (int ni = 0; ni < 8; ni++) {
                int n = wn * 64 + ni * 8 + lc2;
                float2 bb = *(const float2*)(b1 + n);
                #pragma unroll
                for (int mi = 0; mi < 4; mi++) {
                    int m1 = wm * 64 + mi * 16 + lrow;
                    float x0 = frelu(c[mi][ni][0] + bb.x);
                    float x1 = frelu(c[mi][ni][1] + bb.y);
                    float y0 = frelu(c[mi][ni][2] + bb.x);
                    float y1 = frelu(c[mi][ni][3] + bb.y);
                    uint32_t h, l;
                    uint32_t off1 = (uint32_t)m1 * (APITCH * 2) + n * 2;
                    split2h(x0, x1, h, l);
                    *(uint32_t*)(smem + SM_AH + off1) = h;
                    *(uint32_t*)(smem + SM_AL + off1) = l;
                    uint32_t off2 = off1 + 8 * (APITCH * 2);
                    split2h(y0, y1, h, l);
                    *(uint32_t*)(smem + SM_AH + off2) = h;
                    *(uint32_t*)(smem + SM_AL + off2) = l;
                    c[mi][ni][0] = 0.f; c[mi][ni][1] = 0.f;
                    c[mi][ni][2] = 0.f; c[mi][ni][3] = 0.f;
                }
            }
            __syncthreads();
        }
    }

    // ---- final epilogue: logit = relu(D + b2) . Wf + bf
    float* part = (float*)(smem + SM_PART);
    float ps1[4], ps2[4];
    #pragma unroll
    for (int mi = 0; mi < 4; mi++) { ps1[mi] = 0.f; ps2[mi] = 0.f; }
    #pragma unroll
    for (int ni = 0; ni < 8; ni++) {
        int n = wn * 64 + ni * 8 + lc2;
        float2 bb = *(const float2*)(b2 + n);
        float2 wf = *(const float2*)(Wf + n);
        #pragma unroll
        for (int mi = 0; mi < 4; mi++) {
            ps1[mi] = fmaf(frelu(c[mi][ni][0] + bb.x), wf.x, ps1[mi]);
            ps1[mi] = fmaf(frelu(c[mi][ni][1] + bb.y), wf.y, ps1[mi]);
            ps2[mi] = fmaf(frelu(c[mi][ni][2] + bb.x), wf.x, ps2[mi]);
            ps2[mi] = fmaf(frelu(c[mi][ni][3] + bb.y), wf.y, ps2[mi]);
        }
    }
    #pragma unroll
    for (int mi = 0; mi < 4; mi++) {
        ps1[mi] += __shfl_xor_sync(0xffffffffu, ps1[mi], 1);
        ps1[mi] += __shfl_xor_sync(0xffffffffu, ps1[mi], 2);
        ps2[mi] += __shfl_xor_sync(0xffffffffu, ps2[mi], 1);
        ps2[mi] += __shfl_xor_sync(0xffffffffu, ps2[mi], 2);
    }
    if ((lt & 3) == 0) {
        #pragma unroll
        for (int mi = 0; mi < 4; mi++) {
            int m1 = wm * 64 + mi * 16 + lrow;
            part[wn * 128 + m1]     = ps1[mi];
            part[wn * 128 + m1 + 8] = ps2[mi];
        }
    }
    __syncthreads();
    if (tid < 128) {
        float s = part[tid] + part[128 + tid] + part[256 + tid] + part[384 + tid]
                + __ldg(bf);
        out[(size_t)qrow * SKd + kb * 128 + tid] = s;
    }
}

// ---------------------------------------------------------------------------
// Launch (3 launches per call)
// ---------------------------------------------------------------------------
extern "C" void kernel_launch(void* const* d_in, const int* in_sizes, int n_in,
                              void* d_out, int out_size)
{
    (void)in_sizes; (void)n_in; (void)out_size;
    const float* query = (const float*)d_in[0];
    const float* key_  = (const float*)d_in[1];
    const float* Wqe   = (const float*)d_in[2];
    const float* bqe   = (const float*)d_in[3];
    const float* Wke   = (const float*)d_in[4];
    const float* bke   = (const float*)d_in[5];
    const float* W0    = (const float*)d_in[6];
    const float* b0    = (const float*)d_in[7];
    const float* W1    = (const float*)d_in[8];
    const float* b1    = (const float*)d_in[9];
    const float* W2    = (const float*)d_in[10];
    const float* b2    = (const float*)d_in[11];
    const float* Wf    = (const float*)d_in[12];
    const float* bf    = (const float*)d_in[13];
    const float* Wv1   = (const float*)d_in[14];
    const float* bv1   = (const float*)d_in[15];
    const float* Wv2   = (const float*)d_in[16];
    const float* bv2   = (const float*)d_in[17];
    float* out = (float*)d_out;

    cudaFuncSetAttribute(pair_mma_kernel,
                         cudaFuncAttributeMaxDynamicSharedMemorySize, SMEM_TOTAL);

    // 1: encoders (qf, kf)
    encoder_kernel<<<dim3(4, 48), 256>>>(query, key_, Wqe, bqe, Wke, bke);
    // 2: projections (qp,kp,qv,kv) + W1/W2 transpose (fp16)
    proj_trans_kernel<<<dim3(4, 32, 5), 256>>>(W0, Wv1, W1, W2);
    // 3: fused HMMA pair MLP (2-term split, 256 threads)
    pair_mma_kernel<<<dim3(SKd / 128, SQd, Bsz), 256, SMEM_TOTAL>>>(
        b0, b1, b2, Wf, bf, bv1, Wv2, bv2, out);
}

// round 11
// speedup vs baseline: 1.5844x; 1.4458x over previous
#include <cuda_runtime.h>
#include <cuda_fp16.h>
#include <math.h>
#include <cstdint>

// Problem constants
#define Bsz 2
#define SQd 256
#define SKd 512
#define Ed  512
#define Hd  256

#define NQ (Bsz*SQd)   // 512
#define NK (Bsz*SKd)   // 1024
#define OFF_QF 0
#define OFF_KF (OFF_QF + NQ*Hd)
#define OFF_QP (OFF_KF + NK*Hd)
#define OFF_KP (OFF_QP + NQ*Hd)
#define OFF_QV (OFF_KP + NK*Hd)
#define OFF_KV (OFF_QV + NQ*Hd)
#define SCRATCH_FLOATS (OFF_KV + NK*Hd)

__device__ float g_scratch[SCRATCH_FLOATS];
// Transposed fp16 weights: [W1h][W2h], each [256 n][256 k]
__device__ __align__(16) __half g_wt[2 * 256 * 256];

__device__ __forceinline__ float frelu(float x) { return x > 0.f ? x : 0.f; }
__device__ __forceinline__ float4 ldg4(const float* p) { return __ldg((const float4*)p); }

__device__ __forceinline__ uint32_t smem_to_u32(const void* p) {
    uint32_t a;
    asm("{ .reg .u64 t; cvta.to.shared.u64 t, %1; cvt.u32.u64 %0, t; }" : "=r"(a) : "l"(p));
    return a;
}
__device__ __forceinline__ void cp16(uint32_t dst, const void* src) {
    asm volatile("cp.async.cg.shared.global [%0], [%1], 16;" :: "r"(dst), "l"(src));
}
#define CP_COMMIT() asm volatile("cp.async.commit_group;" ::: "memory")
#define CP_WAIT0()  asm volatile("cp.async.wait_group 0;" ::: "memory")

// fp16 inputs, fp32 accumulate
__device__ __forceinline__ void mma_f32acc(float* c, const uint32_t* a, const uint32_t* b) {
    asm volatile(
        "mma.sync.aligned.m16n8k16.row.col.f32.f16.f16.f32 "
        "{%0,%1,%2,%3}, {%4,%5,%6,%7}, {%8,%9}, {%0,%1,%2,%3};"
        : "+f"(c[0]), "+f"(c[1]), "+f"(c[2]), "+f"(c[3])
        : "r"(a[0]), "r"(a[1]), "r"(a[2]), "r"(a[3]), "r"(b[0]), "r"(b[1]));
}
__device__ __forceinline__ void ldsm4(uint32_t* r, uint32_t addr) {
    asm volatile("ldmatrix.sync.aligned.m8n8.x4.shared.b16 {%0,%1,%2,%3}, [%4];"
                 : "=r"(r[0]), "=r"(r[1]), "=r"(r[2]), "=r"(r[3]) : "r"(addr));
}
// pack two fp32 -> fp16x2
__device__ __forceinline__ uint32_t pack2h(float x0, float x1) {
    __half2 p = __floats2half2_rn(x0, x1);
    return *reinterpret_cast<uint32_t*>(&p);
}

// ---------------------------------------------------------------------------
// Prep GEMM tile: cp.async double-buffered (verified R9). 256 threads, 32x64.
// ---------------------------------------------------------------------------
__device__ void gemm_tile(const float* __restrict__ A,
                          const float* __restrict__ W,
                          const float* __restrict__ bias,
                          float* __restrict__ C,
                          int K, int act, int row0, int col0)
{
    __shared__ float As[2][32 * 32];
    __shared__ float Ws[2][32 * 64];
    const int tid = threadIdx.x;
    const int tr  = tid >> 4;
    const int tc  = tid & 15;
    const uint32_t as0 = smem_to_u32(As);
    const uint32_t ws0 = smem_to_u32(Ws);

    const int lr  = tid >> 3;          // A loader: row 0..31
    const int lck = (tid & 7) * 4;     // A loader: col group

    // prefetch chunk 0
    cp16(as0 + (uint32_t)(lr * 32 + lck) * 4, A + (size_t)(row0 + lr) * K + lck);
    #pragma unroll
    for (int i = 0; i < 2; i++) {
        int f = tid + 256 * i; int k = f >> 4; int cc = (f & 15) * 4;
        cp16(ws0 + (uint32_t)(k * 64 + cc) * 4, W + (size_t)k * 256 + col0 + cc);
    }
    CP_COMMIT();

    float acc0x=0.f,acc0y=0.f,acc0z=0.f,acc0w=0.f,acc1x=0.f,acc1y=0.f,acc1z=0.f,acc1w=0.f;
    if (bias) {
        float4 bb = ldg4(bias + col0 + tc * 4);
        acc0x=bb.x;acc0y=bb.y;acc0z=bb.z;acc0w=bb.w;
        acc1x=bb.x;acc1y=bb.y;acc1z=bb.z;acc1w=bb.w;
    }

    const int nch = K >> 5;
    for (int g = 0; g < nch; g++) {
        CP_WAIT0();
        __syncthreads();
        if (g + 1 < nch) {
            int kc = (g + 1) * 32;
            uint32_t bsel = (uint32_t)((g + 1) & 1);
            cp16(as0 + bsel * 4096 + (uint32_t)(lr * 32 + lck) * 4,
                 A + (size_t)(row0 + lr) * K + kc + lck);
            #pragma unroll
            for (int i = 0; i < 2; i++) {
                int f = tid + 256 * i; int k = f >> 4; int cc = (f & 15) * 4;
                cp16(ws0 + bsel * 8192 + (uint32_t)(k * 64 + cc) * 4,
                     W + (size_t)(kc + k) * 256 + col0 + cc);
            }
            CP_COMMIT();
        }
        const float* Asb = As[g & 1];
        const float* Wsb = Ws[g & 1];
        #pragma unroll 8
        for (int k = 0; k < 32; k++) {
            float a0 = Asb[(tr * 2) * 32 + k];
            float a1 = Asb[(tr * 2 + 1) * 32 + k];
            float4 w = *(const float4*)(Wsb + k * 64 + tc * 4);
            acc0x = fmaf(a0, w.x, acc0x); acc0y = fmaf(a0, w.y, acc0y);
            acc0z = fmaf(a0, w.z, acc0z); acc0w = fmaf(a0, w.w, acc0w);
            acc1x = fmaf(a1, w.x, acc1x); acc1y = fmaf(a1, w.y, acc1y);
            acc1z = fmaf(a1, w.z, acc1z); acc1w = fmaf(a1, w.w, acc1w);
        }
    }
    if (act) {
        acc0x=frelu(acc0x);acc0y=frelu(acc0y);acc0z=frelu(acc0z);acc0w=frelu(acc0w);
        acc1x=frelu(acc1x);acc1y=frelu(acc1y);acc1z=frelu(acc1z);acc1w=frelu(acc1w);
    }
    *(float4*)(C + (size_t)(row0+tr*2)  *256 + col0 + tc*4) = make_float4(acc0x,acc0y,acc0z,acc0w);
    *(float4*)(C + (size_t)(row0+tr*2+1)*256 + col0 + tc*4) = make_float4(acc1x,acc1y,acc1z,acc1w);
}

// Launch 1: both encoders. grid (4, 48)
__global__ void encoder_kernel(const float* __restrict__ query,
                               const float* __restrict__ key_,
                               const float* __restrict__ Wqe, const float* __restrict__ bqe,
                               const float* __restrict__ Wke, const float* __restrict__ bke)
{
    float* S = g_scratch;
    int y = blockIdx.y;
    if (y < 16)
        gemm_tile(query, Wqe, bqe, S + OFF_QF, Ed, 1, y * 32, blockIdx.x * 64);
    else
        gemm_tile(key_,  Wke, bke, S + OFF_KF, Ed, 1, (y - 16) * 32, blockIdx.x * 64);
}

// Launch 2: 4 projections (b0 folded into qp, bv1 into qv) + W transpose (fp16).
// grid (4, 32, 5)
__global__ void proj_trans_kernel(const float* __restrict__ W0,
                                  const float* __restrict__ Wv1,
                                  const float* __restrict__ W1,
                                  const float* __restrict__ W2,
                                  const float* __restrict__ b0,
                                  const float* __restrict__ bv1)
{
    float* S = g_scratch;
    const int z = blockIdx.z;
    if (z < 4) {
        const float* A; const float* W; float* C; const float* bias;
        switch (z) {
            case 0: A = S + OFF_QF; W = W0;            C = S + OFF_QP; bias = b0;     break;
            case 1: A = S + OFF_KF; W = W0 + Hd * Hd;  C = S + OFF_KP; bias = nullptr;break;
            case 2: A = S + OFF_QF; W = Wv1;           C = S + OFF_QV; bias = bv1;    break;
            default:A = S + OFF_KF; W = Wv1 + Hd * Hd; C = S + OFF_KV; bias = nullptr;break;
        }
        int M = (z == 1 || z == 3) ? 1024 : 512;
        if (blockIdx.y * 32 >= M) return;
        gemm_tile(A, W, bias, C, Hd, 0, blockIdx.y * 32, blockIdx.x * 64);
    } else {
        // transpose + fp16 round of W1, W2 into g_wt (Wt[n][k] row-major)
        int lin = blockIdx.y * 4 + blockIdx.x;      // 0..127
        const float* W = (lin >= 64) ? W2 : W1;
        __half* oh = g_wt + (size_t)(lin >= 64 ? 1 : 0) * 65536;
        int base = (lin & 63) * 1024;
        #pragma unroll
        for (int t = 0; t < 4; t++) {
            int e = base + t * 256 + threadIdx.x;
            int n = e >> 8, k = e & 255;
            oh[e] = __float2half_rn(__ldg(W + (size_t)k * 256 + n));
        }
    }
}

// ---------------------------------------------------------------------------
// HMMA fused pair kernel: single-term fp16 GEMM (A and W both fp16, f32 acc).
// CTA = (b, q, 128 k-pairs). M=128, N=256, K=256. 256 threads, 8 warps 2Mx4N.
// ---------------------------------------------------------------------------
#define APITCH 264                       // fp16 elems per A row (528 B)
#define SM_AH 0
#define SM_W  (128 * APITCH * 2)         // 67584
#define WBUF_BYTES (256 * 40 * 2)        // 20480, pitch 80 B
#define SM_PART (SM_W + 2 * WBUF_BYTES)  // 108544
#define SMEM_TOTAL (SM_PART + 512 * 4)   // 110592

__global__ void __launch_bounds__(256, 1)
pair_mma_kernel(const float* __restrict__ b1, const float* __restrict__ b2,
                const float* __restrict__ Wf, const float* __restrict__ bf,
                const float* __restrict__ Wv2, const float* __restrict__ bv2,
                float* __restrict__ out)
{
    extern __shared__ char smem[];
    const uint32_t sbase = smem_to_u32(smem);

    const int tid = threadIdx.x;
    const int w   = tid >> 5;
    const int wm  = w >> 2;            // 0..1 : M group (64 rows)
    const int wn  = w & 3;             // 0..3 : N group (64 cols)
    const int lt  = tid & 31;
    const int lrow = lt >> 2;          // 0..7
    const int lc2  = (lt & 3) * 2;     // 0,2,4,6

    // ldmatrix per-lane row offsets
    const uint32_t a_rowoff = (uint32_t)(wm * 64 + (lt & 15)) * (APITCH * 2)
                            + (uint32_t)((lt >> 4) * 8) * 2;
    const uint32_t b_rowoff = (uint32_t)(wn * 64 + (lt & 7) + ((lt >> 4) & 1) * 8) * 80
                            + (uint32_t)((lt >> 3) & 1) * 16;

    const int kb = blockIdx.x, q = blockIdx.y, b = blockIdx.z;
    const int qrow  = b * SQd + q;
    const int krow0 = b * SKd + kb * 128;

    const float* qp = g_scratch + OFF_QP + (size_t)qrow  * Hd;   // b0 pre-folded
    const float* kp = g_scratch + OFF_KP + (size_t)krow0 * Hd;
    const float* qv = g_scratch + OFF_QV + (size_t)qrow  * Hd;   // bv1 pre-folded
    const float* kv = g_scratch + OFF_KV + (size_t)krow0 * Hd;

    // ---- prefetch W chunk 0 (layer 0) via cp.async
    {
        #pragma unroll
        for (int it = 0; it < 4; it++) {
            int u = tid + it * 256;             // 0..1023
            int n = u >> 2, j = u & 3;
            cp16(sbase + SM_W + n * 80 + j * 16, g_wt + n * 256 + j * 8);
        }
        CP_COMMIT();
    }

    // ---- variance branch: v = relu(qv'+kv); softplus(v.Wv2 + bv2)
    {
        const int r = tid >> 1, part = tid & 1;
        const float* qvr = qv + part * 128;
        const float* kvr = kv + (size_t)r * Hd + part * 128;
        const float* wvr = Wv2 + part * 128;
        float s = 0.f;
        #pragma unroll
        for (int i = 0; i < 32; i++) {
            float4 a = ldg4(qvr + i * 4);
            float4 c = ldg4(kvr + i * 4);
            float4 ww = ldg4(wvr + i * 4);
            s = fmaf(frelu(a.x + c.x), ww.x, s);
            s = fmaf(frelu(a.y + c.y), ww.y, s);
            s = fmaf(frelu(a.z + c.z), ww.z, s);
            s = fmaf(frelu(a.w + c.w), ww.w, s);
        }
        s += __shfl_down_sync(0xffffffffu, s, 1);
        if (part == 0) {
            float x = s + __ldg(bv2);
            out[(size_t)Bsz * SQd * SKd + (size_t)qrow * SKd + kb * 128 + r] =
                fmaxf(x, 0.f) + log1pf(expf(-fabsf(x)));
        }
    }

    // ---- build A = relu(qp' + kp) -> fp16 -> SMEM
    {
        const int row = tid >> 1, half = (tid & 1) * 128;
        const float* qpr = qp + half;
        const float* kpr = kp + (size_t)row * Hd + half;
        #pragma unroll
        for (int j4 = 0; j4 < 32; j4++) {
            float4 a  = ldg4(qpr + j4 * 4);
            float4 c  = ldg4(kpr + j4 * 4);
            uint32_t h0 = pack2h(frelu(a.x + c.x), frelu(a.y + c.y));
            uint32_t h1 = pack2h(frelu(a.z + c.z), frelu(a.w + c.w));
            uint32_t off = (uint32_t)row * (APITCH * 2) + (half + j4 * 4) * 2;
            *(uint2*)(smem + SM_AH + off) = make_uint2(h0, h1);
        }
    }
    CP_WAIT0();
    __syncthreads();

    // ---- accumulators: fp32 c[4][8][4]
    float c[4][8][4];
    #pragma unroll
    for (int mi = 0; mi < 4; mi++)
        #pragma unroll
        for (int ni = 0; ni < 8; ni++)
            #pragma unroll
            for (int jj = 0; jj < 4; jj++) c[mi][ni][jj] = 0.f;

    // ---- 16 chunks of K=32: layer = g>>3, kc = g&7; double-buffered cp.async
    #pragma unroll 1
    for (int g = 0; g < 16; g++) {
        const int kc = g & 7;
        const uint32_t wbufH = sbase + SM_W + (uint32_t)(g & 1) * WBUF_BYTES;

        // prefetch next chunk
        if (g + 1 < 16) {
            const __half* Wh = g_wt + (size_t)((g + 1) >> 3) * 65536;
            const int nkc = (g + 1) & 7;
            const uint32_t dbase = sbase + SM_W + ((g + 1) & 1) * WBUF_BYTES;
            #pragma unroll
            for (int it = 0; it < 4; it++) {
                int u = tid + it * 256;
                int n = u >> 2, j = u & 3;
                cp16(dbase + n * 80 + j * 16, Wh + n * 256 + nkc * 32 + j * 8);
            }
            CP_COMMIT();
        }

        // compute on current chunk: 2 k16 steps
        #pragma unroll
        for (int ks = 0; ks < 2; ks++) {
            const uint32_t a_k = (uint32_t)(kc * 32 + ks * 16) * 2;
            const uint32_t b_k = (uint32_t)ks * 32;

            uint32_t afh[4][4], bh[8][2];
            #pragma unroll
            for (int mi = 0; mi < 4; mi++)
                ldsm4(afh[mi], sbase + SM_AH + a_rowoff + (uint32_t)mi * 16 * (APITCH * 2) + a_k);
            #pragma unroll
            for (int np = 0; np < 4; np++) {
                uint32_t r[4];
                ldsm4(r, wbufH + b_rowoff + (uint32_t)np * 16 * 80 + b_k);
                bh[2*np][0] = r[0]; bh[2*np][1] = r[1];
                bh[2*np+1][0] = r[2]; bh[2*np+1][1] = r[3];
            }
            #pragma unroll
            for (int mi = 0; mi < 4; mi++)
                #pragma unroll
                for (int ni = 0; ni < 8; ni++)
                    mma_f32acc(c[mi][ni], afh[mi], bh[ni]);
        }

        CP_WAIT0();
        __syncthreads();

        // ---- between layers: h1 = relu(D + b1) -> fp16 -> A SMEM; reset accum
        if (g == 7) {
            #pragma unroll
            for (int ni = 0; ni < 8; ni++) {
                int n = wn * 64 + ni * 8 + lc2;
                float2 bb = *(const float2*)(b1 + n);
                #pragma unroll
                for (int mi = 0; mi < 4; mi++) {
                    int m1 = wm * 64 + mi * 16 + lrow;
                    uint32_t off1 = (uint32_t)m1 * (APITCH * 2) + n * 2;
                    *(uint32_t*)(smem + SM_AH + off1) =
                        pack2h(frelu(c[mi][ni][0] + bb.x), frelu(c[mi][ni][1] + bb.y));
                    uint32_t off2 = off1 + 8 * (APITCH * 2);
                    *(uint32_t*)(smem + SM_AH + off2) =
                        pack2h(frelu(c[mi][ni][2] + bb.x), frelu(c[mi][ni][3] + bb.y));
                    c[mi][ni][0] = 0.f; c[mi][ni][1] = 0.f;
                    c[mi][ni][2] = 0.f; c[mi][ni][3] = 0.f;
                }
            }
            __syncthreads();
        }
    }

    // ---- final epilogue: logit = relu(D + b2) . Wf + bf
    float* part = (float*)(smem + SM_PART);
    float ps1[4], ps2[4];
    #pragma unroll
    for (int mi = 0; mi < 4; mi++) { ps1[mi] = 0.f; ps2[mi] = 0.f; }
    #pragma unroll
    for (int ni = 0; ni < 8; ni++) {
        int n = wn * 64 + ni * 8 + lc2;
        float2 bb = *(const float2*)(b2 + n);
        float2 wf = *(const float2*)(Wf + n);
        #pragma unroll
        for (int mi = 0; mi < 4; mi++) {
            ps1[mi] = fmaf(frelu(c[mi][ni][0] + bb.x), wf.x, ps1[mi]);
            ps1[mi] = fmaf(frelu(c[mi][ni][1] + bb.y), wf.y, ps1[mi]);
            ps2[mi] = fmaf(frelu(c[mi][ni][2] + bb.x), wf.x, ps2[mi]);
            ps2[mi] = fmaf(frelu(c[mi][ni][3] + bb.y), wf.y, ps2[mi]);
        }
    }
    #pragma unroll
    for (int mi = 0; mi < 4; mi++) {
        ps1[mi] += __shfl_xor_sync(0xffffffffu, ps1[mi], 1);
        ps1[mi] += __shfl_xor_sync(0xffffffffu, ps1[mi], 2);
        ps2[mi] += __shfl_xor_sync(0xffffffffu, ps2[mi], 1);
        ps2[mi] += __shfl_xor_sync(0xffffffffu, ps2[mi], 2);
    }
    if ((lt & 3) == 0) {
        #pragma unroll
        for (int mi = 0; mi < 4; mi++) {
            int m1 = wm * 64 + mi * 16 + lrow;
            part[wn * 128 + m1]     = ps1[mi];
            part[wn * 128 + m1 + 8] = ps2[mi];
        }
    }
    __syncthreads();
    if (tid < 128) {
        float s = part[tid] + part[128 + tid] + part[256 + tid] + part[384 + tid]
                + __ldg(bf);
        out[(size_t)qrow * SKd + kb * 128 + tid] = s;
    }
}

// ---------------------------------------------------------------------------
// Launch (3 launches per call)
// ---------------------------------------------------------------------------
extern "C" void kernel_launch(void* const* d_in, const int* in_sizes, int n_in,
                              void* d_out, int out_size)
{
    (void)in_sizes; (void)n_in; (void)out_size;
    const float* query = (const float*)d_in[0];
    const float* key_  = (const float*)d_in[1];
    const float* Wqe   = (const float*)d_in[2];
    const float* bqe   = (const float*)d_in[3];
    const float* Wke   = (const float*)d_in[4];
    const float* bke   = (const float*)d_in[5];
    const float* W0    = (const float*)d_in[6];
    const float* b0    = (const float*)d_in[7];
    const float* W1    = (const float*)d_in[8];
    const float* b1    = (const float*)d_in[9];
    const float* W2    = (const float*)d_in[10];
    const float* b2    = (const float*)d_in[11];
    const float* Wf    = (const float*)d_in[12];
    const float* bf    = (const float*)d_in[13];
    const float* Wv1   = (const float*)d_in[14];
    const float* bv1   = (const float*)d_in[15];
    const float* Wv2   = (const float*)d_in[16];
    const float* bv2   = (const float*)d_in[17];
    float* out = (float*)d_out;

    cudaFuncSetAttribute(pair_mma_kernel,
                         cudaFuncAttributeMaxDynamicSharedMemorySize, SMEM_TOTAL);

    // 1: encoders (qf, kf)
    encoder_kernel<<<dim3(4, 48), 256>>>(query, key_, Wqe, bqe, Wke, bke);
    // 2: projections (qp+b0, kp, qv+bv1, kv) + W1/W2 transpose (fp16)
    proj_trans_kernel<<<dim3(4, 32, 5), 256>>>(W0, Wv1, W1, W2, b0, bv1);
    // 3: fused HMMA pair MLP (single-term fp16)
    pair_mma_kernel<<<dim3(SKd / 128, SQd, Bsz), 256, SMEM_TOTAL>>>(
        b1, b2, Wf, bf, Wv2, bv2, out);
}

// round 12
// speedup vs baseline: 1.6458x; 1.0387x over previous
#include <cuda_runtime.h>
#include <cuda_fp16.h>
#include <math.h>
#include <cstdint>

// Problem constants
#define Bsz 2
#define SQd 256
#define SKd 512
#define Ed  512
#define Hd  256

#define NQ (Bsz*SQd)   // 512
#define NK (Bsz*SKd)   // 1024
#define OFF_QF 0
#define OFF_KF (OFF_QF + NQ*Hd)
#define OFF_QP (OFF_KF + NK*Hd)
#define OFF_KP (OFF_QP + NQ*Hd)
#define OFF_QV (OFF_KP + NK*Hd)
#define OFF_KV (OFF_QV + NQ*Hd)
#define SCRATCH_FLOATS (OFF_KV + NK*Hd)

__device__ float g_scratch[SCRATCH_FLOATS];
// Transposed fp16 weights: [W1h][W2h], each [256 n][256 k]
__device__ __align__(16) __half g_wt[2 * 256 * 256];

__device__ __forceinline__ float frelu(float x) { return x > 0.f ? x : 0.f; }
__device__ __forceinline__ float4 ldg4(const float* p) { return __ldg((const float4*)p); }

__device__ __forceinline__ uint32_t smem_to_u32(const void* p) {
    uint32_t a;
    asm("{ .reg .u64 t; cvta.to.shared.u64 t, %1; cvt.u32.u64 %0, t; }" : "=r"(a) : "l"(p));
    return a;
}
__device__ __forceinline__ void cp16(uint32_t dst, const void* src) {
    asm volatile("cp.async.cg.shared.global [%0], [%1], 16;" :: "r"(dst), "l"(src));
}
#define CP_COMMIT() asm volatile("cp.async.commit_group;" ::: "memory")
#define CP_WAIT0()  asm volatile("cp.async.wait_group 0;" ::: "memory")

// fp16 inputs, fp32 accumulate
__device__ __forceinline__ void mma_f32acc(float* c, const uint32_t* a, const uint32_t* b) {
    asm volatile(
        "mma.sync.aligned.m16n8k16.row.col.f32.f16.f16.f32 "
        "{%0,%1,%2,%3}, {%4,%5,%6,%7}, {%8,%9}, {%0,%1,%2,%3};"
        : "+f"(c[0]), "+f"(c[1]), "+f"(c[2]), "+f"(c[3])
        : "r"(a[0]), "r"(a[1]), "r"(a[2]), "r"(a[3]), "r"(b[0]), "r"(b[1]));
}
__device__ __forceinline__ void ldsm4(uint32_t* r, uint32_t addr) {
    asm volatile("ldmatrix.sync.aligned.m8n8.x4.shared.b16 {%0,%1,%2,%3}, [%4];"
                 : "=r"(r[0]), "=r"(r[1]), "=r"(r[2]), "=r"(r[3]) : "r"(addr));
}
// pack two fp32 -> fp16x2
__device__ __forceinline__ uint32_t pack2h(float x0, float x1) {
    __half2 p = __floats2half2_rn(x0, x1);
    return *reinterpret_cast<uint32_t*>(&p);
}

// ---------------------------------------------------------------------------
// Prep GEMM tile: cp.async double-buffered (verified R9). 256 threads, 32x64.
// ---------------------------------------------------------------------------
__device__ void gemm_tile(const float* __restrict__ A,
                          const float* __restrict__ W,
                          const float* __restrict__ bias,
                          float* __restrict__ C,
                          int K, int act, int row0, int col0)
{
    __shared__ float As[2][32 * 32];
    __shared__ float Ws[2][32 * 64];
    const int tid = threadIdx.x;
    const int tr  = tid >> 4;
    const int tc  = tid & 15;
    const uint32_t as0 = smem_to_u32(As);
    const uint32_t ws0 = smem_to_u32(Ws);

    const int lr  = tid >> 3;          // A loader: row 0..31
    const int lck = (tid & 7) * 4;     // A loader: col group

    // prefetch chunk 0
    cp16(as0 + (uint32_t)(lr * 32 + lck) * 4, A + (size_t)(row0 + lr) * K + lck);
    #pragma unroll
    for (int i = 0; i < 2; i++) {
        int f = tid + 256 * i; int k = f >> 4; int cc = (f & 15) * 4;
        cp16(ws0 + (uint32_t)(k * 64 + cc) * 4, W + (size_t)k * 256 + col0 + cc);
    }
    CP_COMMIT();

    float acc0x=0.f,acc0y=0.f,acc0z=0.f,acc0w=0.f,acc1x=0.f,acc1y=0.f,acc1z=0.f,acc1w=0.f;
    if (bias) {
        float4 bb = ldg4(bias + col0 + tc * 4);
        acc0x=bb.x;acc0y=bb.y;acc0z=bb.z;acc0w=bb.w;
        acc1x=bb.x;acc1y=bb.y;acc1z=bb.z;acc1w=bb.w;
    }

    const int nch = K >> 5;
    for (int g = 0; g < nch; g++) {
        CP_WAIT0();
        __syncthreads();
        if (g + 1 < nch) {
            int kc = (g + 1) * 32;
            uint32_t bsel = (uint32_t)((g + 1) & 1);
            cp16(as0 + bsel * 4096 + (uint32_t)(lr * 32 + lck) * 4,
                 A + (size_t)(row0 + lr) * K + kc + lck);
            #pragma unroll
            for (int i = 0; i < 2; i++) {
                int f = tid + 256 * i; int k = f >> 4; int cc = (f & 15) * 4;
                cp16(ws0 + bsel * 8192 + (uint32_t)(k * 64 + cc) * 4,
                     W + (size_t)(kc + k) * 256 + col0 + cc);
            }
            CP_COMMIT();
        }
        const float* Asb = As[g & 1];
        const float* Wsb = Ws[g & 1];
        #pragma unroll 8
        for (int k = 0; k < 32; k++) {
            float a0 = Asb[(tr * 2) * 32 + k];
            float a1 = Asb[(tr * 2 + 1) * 32 + k];
            float4 w = *(const float4*)(Wsb + k * 64 + tc * 4);
            acc0x = fmaf(a0, w.x, acc0x); acc0y = fmaf(a0, w.y, acc0y);
            acc0z = fmaf(a0, w.z, acc0z); acc0w = fmaf(a0, w.w, acc0w);
            acc1x = fmaf(a1, w.x, acc1x); acc1y = fmaf(a1, w.y, acc1y);
            acc1z = fmaf(a1, w.z, acc1z); acc1w = fmaf(a1, w.w, acc1w);
        }
    }
    if (act) {
        acc0x=frelu(acc0x);acc0y=frelu(acc0y);acc0z=frelu(acc0z);acc0w=frelu(acc0w);
        acc1x=frelu(acc1x);acc1y=frelu(acc1y);acc1z=frelu(acc1z);acc1w=frelu(acc1w);
    }
    *(float4*)(C + (size_t)(row0+tr*2)  *256 + col0 + tc*4) = make_float4(acc0x,acc0y,acc0z,acc0w);
    *(float4*)(C + (size_t)(row0+tr*2+1)*256 + col0 + tc*4) = make_float4(acc1x,acc1y,acc1z,acc1w);
}

// Launch 1: both encoders. grid (4, 48)
__global__ void encoder_kernel(const float* __restrict__ query,
                               const float* __restrict__ key_,
                               const float* __restrict__ Wqe, const float* __restrict__ bqe,
                               const float* __restrict__ Wke, const float* __restrict__ bke)
{
    float* S = g_scratch;
    int y = blockIdx.y;
    if (y < 16)
        gemm_tile(query, Wqe, bqe, S + OFF_QF, Ed, 1, y * 32, blockIdx.x * 64);
    else
        gemm_tile(key_,  Wke, bke, S + OFF_KF, Ed, 1, (y - 16) * 32, blockIdx.x * 64);
}

// Launch 2: 4 projections (b0 folded into qp, bv1 into qv) + W transpose (fp16).
// grid (4, 32, 5)
__global__ void proj_trans_kernel(const float* __restrict__ W0,
                                  const float* __restrict__ Wv1,
                                  const float* __restrict__ W1,
                                  const float* __restrict__ W2,
                                  const float* __restrict__ b0,
                                  const float* __restrict__ bv1)
{
    float* S = g_scratch;
    const int z = blockIdx.z;
    if (z < 4) {
        const float* A; const float* W; float* C; const float* bias;
        switch (z) {
            case 0: A = S + OFF_QF; W = W0;            C = S + OFF_QP; bias = b0;     break;
            case 1: A = S + OFF_KF; W = W0 + Hd * Hd;  C = S + OFF_KP; bias = nullptr;break;
            case 2: A = S + OFF_QF; W = Wv1;           C = S + OFF_QV; bias = bv1;    break;
            default:A = S + OFF_KF; W = Wv1 + Hd * Hd; C = S + OFF_KV; bias = nullptr;break;
        }
        int M = (z == 1 || z == 3) ? 1024 : 512;
        if (blockIdx.y * 32 >= M) return;
        gemm_tile(A, W, bias, C, Hd, 0, blockIdx.y * 32, blockIdx.x * 64);
    } else {
        // transpose + fp16 round of W1, W2 into g_wt (Wt[n][k] row-major)
        int lin = blockIdx.y * 4 + blockIdx.x;      // 0..127
        const float* W = (lin >= 64) ? W2 : W1;
        __half* oh = g_wt + (size_t)(lin >= 64 ? 1 : 0) * 65536;
        int base = (lin & 63) * 1024;
        #pragma unroll
        for (int t = 0; t < 4; t++) {
            int e = base + t * 256 + threadIdx.x;
            int n = e >> 8, k = e & 255;
            oh[e] = __float2half_rn(__ldg(W + (size_t)k * 256 + n));
        }
    }
}

// ---------------------------------------------------------------------------
// HMMA fused pair kernel: single-term fp16 GEMM, K=64 chunks (8 total).
// CTA = (b, q, 128 k-pairs). M=128, N=256, K=256. 256 threads, 8 warps 2Mx4N.
// ---------------------------------------------------------------------------
#define APITCH 264                       // fp16 elems per A row (528 B)
#define SM_AH 0
#define SM_W  (128 * APITCH * 2)         // 67584
#define WPITCH 144                       // bytes per W chunk row (64 fp16 + pad)
#define WBUF_BYTES (256 * WPITCH)        // 36864
#define SM_PART (SM_W + 2 * WBUF_BYTES)  // 141312
#define SMEM_TOTAL (SM_PART + 512 * 4)   // 143360

__global__ void __launch_bounds__(256, 1)
pair_mma_kernel(const float* __restrict__ b1, const float* __restrict__ b2,
                const float* __restrict__ Wf, const float* __restrict__ bf,
                const float* __restrict__ Wv2, const float* __restrict__ bv2,
                float* __restrict__ out)
{
    extern __shared__ char smem[];
    const uint32_t sbase = smem_to_u32(smem);

    const int tid = threadIdx.x;
    const int w   = tid >> 5;
    const int wm  = w >> 2;            // 0..1 : M group (64 rows)
    const int wn  = w & 3;             // 0..3 : N group (64 cols)
    const int lt  = tid & 31;
    const int lrow = lt >> 2;          // 0..7
    const int lc2  = (lt & 3) * 2;     // 0,2,4,6

    // ldmatrix per-lane row offsets
    const uint32_t a_rowoff = (uint32_t)(wm * 64 + (lt & 15)) * (APITCH * 2)
                            + (uint32_t)((lt >> 4) * 8) * 2;
    const uint32_t b_rowoff = (uint32_t)(wn * 64 + (lt & 7) + ((lt >> 4) & 1) * 8) * WPITCH
                            + (uint32_t)((lt >> 3) & 1) * 16;

    const int kb = blockIdx.x, q = blockIdx.y, b = blockIdx.z;
    const int qrow  = b * SQd + q;
    const int krow0 = b * SKd + kb * 128;

    const float* qp = g_scratch + OFF_QP + (size_t)qrow  * Hd;   // b0 pre-folded
    const float* kp = g_scratch + OFF_KP + (size_t)krow0 * Hd;
    const float* qv = g_scratch + OFF_QV + (size_t)qrow  * Hd;   // bv1 pre-folded
    const float* kv = g_scratch + OFF_KV + (size_t)krow0 * Hd;

    // ---- prefetch W chunk 0 (layer 0) via cp.async: 256 rows x 128 B
    {
        #pragma unroll
        for (int it = 0; it < 8; it++) {
            int u = tid + it * 256;             // 0..2047
            int n = u >> 3, j = u & 7;
            cp16(sbase + SM_W + n * WPITCH + j * 16, g_wt + n * 256 + j * 8);
        }
        CP_COMMIT();
    }

    // ---- variance branch: v = relu(qv'+kv); softplus(v.Wv2 + bv2)
    {
        const int r = tid >> 1, part = tid & 1;
        const float* qvr = qv + part * 128;
        const float* kvr = kv + (size_t)r * Hd + part * 128;
        const float* wvr = Wv2 + part * 128;
        float s = 0.f;
        #pragma unroll
        for (int i = 0; i < 32; i++) {
            float4 a = ldg4(qvr + i * 4);
            float4 c = ldg4(kvr + i * 4);
            float4 ww = ldg4(wvr + i * 4);
            s = fmaf(frelu(a.x + c.x), ww.x, s);
            s = fmaf(frelu(a.y + c.y), ww.y, s);
            s = fmaf(frelu(a.z + c.z), ww.z, s);
            s = fmaf(frelu(a.w + c.w), ww.w, s);
        }
        s += __shfl_down_sync(0xffffffffu, s, 1);
        if (part == 0) {
            float x = s + __ldg(bv2);
            out[(size_t)Bsz * SQd * SKd + (size_t)qrow * SKd + kb * 128 + r] =
                fmaxf(x, 0.f) + log1pf(expf(-fabsf(x)));
        }
    }

    // ---- build A = relu(qp' + kp) -> fp16 -> SMEM
    {
        const int row = tid >> 1, half = (tid & 1) * 128;
        const float* qpr = qp + half;
        const float* kpr = kp + (size_t)row * Hd + half;
        #pragma unroll
        for (int j4 = 0; j4 < 32; j4++) {
            float4 a  = ldg4(qpr + j4 * 4);
            float4 c  = ldg4(kpr + j4 * 4);
            uint32_t h0 = pack2h(frelu(a.x + c.x), frelu(a.y + c.y));
            uint32_t h1 = pack2h(frelu(a.z + c.z), frelu(a.w + c.w));
            uint32_t off = (uint32_t)row * (APITCH * 2) + (half + j4 * 4) * 2;
            *(uint2*)(smem + SM_AH + off) = make_uint2(h0, h1);
        }
    }
    CP_WAIT0();
    __syncthreads();

    // ---- accumulators: fp32 c[4][8][4]
    float c[4][8][4];
    #pragma unroll
    for (int mi = 0; mi < 4; mi++)
        #pragma unroll
        for (int ni = 0; ni < 8; ni++)
            #pragma unroll
            for (int jj = 0; jj < 4; jj++) c[mi][ni][jj] = 0.f;

    // ---- 2 layers x 4 chunks of K=64; double-buffered cp.async
    #pragma unroll 1
    for (int layer = 0; layer < 2; layer++) {
        #pragma unroll 1
        for (int kc = 0; kc < 4; kc++) {
            const int gg = layer * 4 + kc;
            const uint32_t wbuf = sbase + SM_W + (uint32_t)(gg & 1) * WBUF_BYTES;

            // prefetch next chunk
            if (gg + 1 < 8) {
                const __half* Wh = g_wt + (size_t)((gg + 1) >> 2) * 65536;
                const int nkc = (gg + 1) & 3;
                const uint32_t dbase = sbase + SM_W + ((gg + 1) & 1) * WBUF_BYTES;
                #pragma unroll
                for (int it = 0; it < 8; it++) {
                    int u = tid + it * 256;
                    int n = u >> 3, j = u & 7;
                    cp16(dbase + n * WPITCH + j * 16, Wh + n * 256 + nkc * 64 + j * 8);
                }
                CP_COMMIT();
            }

            // compute on current chunk: 4 k16 steps
            #pragma unroll
            for (int ks = 0; ks < 4; ks++) {
                const uint32_t a_k = (uint32_t)(kc * 64 + ks * 16) * 2;
                const uint32_t b_k = (uint32_t)ks * 32;

                uint32_t afh[4][4], bh[8][2];
                #pragma unroll
                for (int mi = 0; mi < 4; mi++)
                    ldsm4(afh[mi], sbase + SM_AH + a_rowoff + (uint32_t)mi * 16 * (APITCH * 2) + a_k);
                #pragma unroll
                for (int np = 0; np < 4; np++) {
                    uint32_t r[4];
                    ldsm4(r, wbuf + b_rowoff + (uint32_t)np * 16 * WPITCH + b_k);
                    bh[2*np][0] = r[0]; bh[2*np][1] = r[1];
                    bh[2*np+1][0] = r[2]; bh[2*np+1][1] = r[3];
                }
                #pragma unroll
                for (int mi = 0; mi < 4; mi++)
                    #pragma unroll
                    for (int ni = 0; ni < 8; ni++)
                        mma_f32acc(c[mi][ni], afh[mi], bh[ni]);
            }

            CP_WAIT0();
            __syncthreads();
        }

        // ---- between layers: h1 = relu(D + b1) -> fp16 -> A SMEM; reset accum
        if (layer == 0) {
            #pragma unroll
            for (int ni = 0; ni < 8; ni++) {
                int n = wn * 64 + ni * 8 + lc2;
                float2 bb = *(const float2*)(b1 + n);
                #pragma unroll
                for (int mi = 0; mi < 4; mi++) {
                    int m1 = wm * 64 + mi * 16 + lrow;
                    uint32_t off1 = (uint32_t)m1 * (APITCH * 2) + n * 2;
                    *(uint32_t*)(smem + SM_AH + off1) =
                        pack2h(frelu(c[mi][ni][0] + bb.x), frelu(c[mi][ni][1] + bb.y));
                    uint32_t off2 = off1 + 8 * (APITCH * 2);
                    *(uint32_t*)(smem + SM_AH + off2) =
                        pack2h(frelu(c[mi][ni][2] + bb.x), frelu(c[mi][ni][3] + bb.y));
                    c[mi][ni][0] = 0.f; c[mi][ni][1] = 0.f;
                    c[mi][ni][2] = 0.f; c[mi][ni][3] = 0.f;
                }
            }
            __syncthreads();
        }
    }

    // ---- final epilogue: logit = relu(D + b2) . Wf + bf
    float* part = (float*)(smem + SM_PART);
    float ps1[4], ps2[4];
    #pragma unroll
    for (int mi = 0; mi < 4; mi++) { ps1[mi] = 0.f; ps2[mi] = 0.f; }
    #pragma unroll
    for (int ni = 0; ni < 8; ni++) {
        int n = wn * 64 + ni * 8 + lc2;
        float2 bb = *(const float2*)(b2 + n);
        float2 wf = *(const float2*)(Wf + n);
        #pragma unroll
        for (int mi = 0; mi < 4; mi++) {
            ps1[mi] = fmaf(frelu(c[mi][ni][0] + bb.x), wf.x, ps1[mi]);
            ps1[mi] = fmaf(frelu(c[mi][ni][1] + bb.y), wf.y, ps1[mi]);
            ps2[mi] = fmaf(frelu(c[mi][ni][2] + bb.x), wf.x, ps2[mi]);
            ps2[mi] = fmaf(frelu(c[mi][ni][3] + bb.y), wf.y, ps2[mi]);
        }
    }
    #pragma unroll
    for (int mi = 0; mi < 4; mi++) {
        ps1[mi] += __shfl_xor_sync(0xffffffffu, ps1[mi], 1);
        ps1[mi] += __shfl_xor_sync(0xffffffffu, ps1[mi], 2);
        ps2[mi] += __shfl_xor_sync(0xffffffffu, ps2[mi], 1);
        ps2[mi] += __shfl_xor_sync(0xffffffffu, ps2[mi], 2);
    }
    if ((lt & 3) == 0) {
        #pragma unroll
        for (int mi = 0; mi < 4; mi++) {
            int m1 = wm * 64 + mi * 16 + lrow;
            part[wn * 128 + m1]     = ps1[mi];
            part[wn * 128 + m1 + 8] = ps2[mi];
        }
    }
    __syncthreads();
    if (tid < 128) {
        float s = part[tid] + part[128 + tid] + part[256 + tid] + part[384 + tid]
                + __ldg(bf);
        out[(size_t)qrow * SKd + kb * 128 + tid] = s;
    }
}

// ---------------------------------------------------------------------------
// Launch (3 launches per call)
// ---------------------------------------------------------------------------
extern "C" void kernel_launch(void* const* d_in, const int* in_sizes, int n_in,
                              void* d_out, int out_size)
{
    (void)in_sizes; (void)n_in; (void)out_size;
    const float* query = (const float*)d_in[0];
    const float* key_  = (const float*)d_in[1];
    const float* Wqe   = (const float*)d_in[2];
    const float* bqe   = (const float*)d_in[3];
    const float* Wke   = (const float*)d_in[4];
    const float* bke   = (const float*)d_in[5];
    const float* W0    = (const float*)d_in[6];
    const float* b0    = (const float*)d_in[7];
    const float* W1    = (const float*)d_in[8];
    const float* b1    = (const float*)d_in[9];
    const float* W2    = (const float*)d_in[10];
    const float* b2    = (const float*)d_in[11];
    const float* Wf    = (const float*)d_in[12];
    const float* bf    = (const float*)d_in[13];
    const float* Wv1   = (const float*)d_in[14];
    const float* bv1   = (const float*)d_in[15];
    const float* Wv2   = (const float*)d_in[16];
    const float* bv2   = (const float*)d_in[17];
    float* out = (float*)d_out;

    cudaFuncSetAttribute(pair_mma_kernel,
                         cudaFuncAttributeMaxDynamicSharedMemorySize, SMEM_TOTAL);

    // 1: encoders (qf, kf)
    encoder_kernel<<<dim3(4, 48), 256>>>(query, key_, Wqe, bqe, Wke, bke);
    // 2: projections (qp+b0, kp, qv+bv1, kv) + W1/W2 transpose (fp16)
    proj_trans_kernel<<<dim3(4, 32, 5), 256>>>(W0, Wv1, W1, W2, b0, bv1);
    // 3: fused HMMA pair MLP (single-term fp16, K=64 chunks)
    pair_mma_kernel<<<dim3(SKd / 128, SQd, Bsz), 256, SMEM_TOTAL>>>(
        b1, b2, Wf, bf, Wv2, bv2, out);
}

// round 13
// speedup vs baseline: 1.6678x; 1.0134x over previous
#include <cuda_runtime.h>
#include <cuda_fp16.h>
#include <math.h>
#include <cstdint>

// Problem constants
#define Bsz 2
#define SQd 256
#define SKd 512
#define Ed  512
#define Hd  256

#define NQ (Bsz*SQd)   // 512
#define NK (Bsz*SKd)   // 1024
#define OFF_QF 0
#define OFF_KF (OFF_QF + NQ*Hd)
#define OFF_QP (OFF_KF + NK*Hd)
#define OFF_KP (OFF_QP + NQ*Hd)
#define OFF_QV (OFF_KP + NK*Hd)
#define OFF_KV (OFF_QV + NQ*Hd)
#define SCRATCH_FLOATS (OFF_KV + NK*Hd)

__device__ float g_scratch[SCRATCH_FLOATS];
// Transposed fp16 weights: [W1h][W2h], each [256 n][256 k]
__device__ __align__(16) __half g_wt[2 * 256 * 256];

__device__ __forceinline__ float frelu(float x) { return x > 0.f ? x : 0.f; }
__device__ __forceinline__ float4 ldg4(const float* p) { return __ldg((const float4*)p); }

__device__ __forceinline__ uint32_t smem_to_u32(const void* p) {
    uint32_t a;
    asm("{ .reg .u64 t; cvta.to.shared.u64 t, %1; cvt.u32.u64 %0, t; }" : "=r"(a) : "l"(p));
    return a;
}
__device__ __forceinline__ void cp16(uint32_t dst, const void* src) {
    asm volatile("cp.async.cg.shared.global [%0], [%1], 16;" :: "r"(dst), "l"(src));
}
#define CP_COMMIT() asm volatile("cp.async.commit_group;" ::: "memory")
#define CP_WAIT0()  asm volatile("cp.async.wait_group 0;" ::: "memory")

// fp16 inputs, fp32 accumulate
__device__ __forceinline__ void mma_f32acc(float* c, const uint32_t* a, const uint32_t* b) {
    asm volatile(
        "mma.sync.aligned.m16n8k16.row.col.f32.f16.f16.f32 "
        "{%0,%1,%2,%3}, {%4,%5,%6,%7}, {%8,%9}, {%0,%1,%2,%3};"
        : "+f"(c[0]), "+f"(c[1]), "+f"(c[2]), "+f"(c[3])
        : "r"(a[0]), "r"(a[1]), "r"(a[2]), "r"(a[3]), "r"(b[0]), "r"(b[1]));
}
__device__ __forceinline__ void ldsm4(uint32_t* r, uint32_t addr) {
    asm volatile("ldmatrix.sync.aligned.m8n8.x4.shared.b16 {%0,%1,%2,%3}, [%4];"
                 : "=r"(r[0]), "=r"(r[1]), "=r"(r[2]), "=r"(r[3]) : "r"(addr));
}
// pack two fp32 -> fp16x2
__device__ __forceinline__ uint32_t pack2h(float x0, float x1) {
    __half2 p = __floats2half2_rn(x0, x1);
    return *reinterpret_cast<uint32_t*>(&p);
}

// ---------------------------------------------------------------------------
// Prep GEMM tile: cp.async double-buffered (verified R9). 256 threads, 32x64.
// ---------------------------------------------------------------------------
__device__ void gemm_tile(const float* __restrict__ A,
                          const float* __restrict__ W,
                          const float* __restrict__ bias,
                          float* __restrict__ C,
                          int K, int act, int row0, int col0)
{
    __shared__ float As[2][32 * 32];
    __shared__ float Ws[2][32 * 64];
    const int tid = threadIdx.x;
    const int tr  = tid >> 4;
    const int tc  = tid & 15;
    const uint32_t as0 = smem_to_u32(As);
    const uint32_t ws0 = smem_to_u32(Ws);

    const int lr  = tid >> 3;          // A loader: row 0..31
    const int lck = (tid & 7) * 4;     // A loader: col group

    // prefetch chunk 0
    cp16(as0 + (uint32_t)(lr * 32 + lck) * 4, A + (size_t)(row0 + lr) * K + lck);
    #pragma unroll
    for (int i = 0; i < 2; i++) {
        int f = tid + 256 * i; int k = f >> 4; int cc = (f & 15) * 4;
        cp16(ws0 + (uint32_t)(k * 64 + cc) * 4, W + (size_t)k * 256 + col0 + cc);
    }
    CP_COMMIT();

    float acc0x=0.f,acc0y=0.f,acc0z=0.f,acc0w=0.f,acc1x=0.f,acc1y=0.f,acc1z=0.f,acc1w=0.f;
    if (bias) {
        float4 bb = ldg4(bias + col0 + tc * 4);
        acc0x=bb.x;acc0y=bb.y;acc0z=bb.z;acc0w=bb.w;
        acc1x=bb.x;acc1y=bb.y;acc1z=bb.z;acc1w=bb.w;
    }

    const int nch = K >> 5;
    for (int g = 0; g < nch; g++) {
        CP_WAIT0();
        __syncthreads();
        if (g + 1 < nch) {
            int kc = (g + 1) * 32;
            uint32_t bsel = (uint32_t)((g + 1) & 1);
            cp16(as0 + bsel * 4096 + (uint32_t)(lr * 32 + lck) * 4,
                 A + (size_t)(row0 + lr) * K + kc + lck);
            #pragma unroll
            for (int i = 0; i < 2; i++) {
                int f = tid + 256 * i; int k = f >> 4; int cc = (f & 15) * 4;
                cp16(ws0 + bsel * 8192 + (uint32_t)(k * 64 + cc) * 4,
                     W + (size_t)(kc + k) * 256 + col0 + cc);
            }
            CP_COMMIT();
        }
        const float* Asb = As[g & 1];
        const float* Wsb = Ws[g & 1];
        #pragma unroll 8
        for (int k = 0; k < 32; k++) {
            float a0 = Asb[(tr * 2) * 32 + k];
            float a1 = Asb[(tr * 2 + 1) * 32 + k];
            float4 w = *(const float4*)(Wsb + k * 64 + tc * 4);
            acc0x = fmaf(a0, w.x, acc0x); acc0y = fmaf(a0, w.y, acc0y);
            acc0z = fmaf(a0, w.z, acc0z); acc0w = fmaf(a0, w.w, acc0w);
            acc1x = fmaf(a1, w.x, acc1x); acc1y = fmaf(a1, w.y, acc1y);
            acc1z = fmaf(a1, w.z, acc1z); acc1w = fmaf(a1, w.w, acc1w);
        }
    }
    if (act) {
        acc0x=frelu(acc0x);acc0y=frelu(acc0y);acc0z=frelu(acc0z);acc0w=frelu(acc0w);
        acc1x=frelu(acc1x);acc1y=frelu(acc1y);acc1z=frelu(acc1z);acc1w=frelu(acc1w);
    }
    *(float4*)(C + (size_t)(row0+tr*2)  *256 + col0 + tc*4) = make_float4(acc0x,acc0y,acc0z,acc0w);
    *(float4*)(C + (size_t)(row0+tr*2+1)*256 + col0 + tc*4) = make_float4(acc1x,acc1y,acc1z,acc1w);
}

// Launch 1: both encoders. grid (4, 48)
__global__ void encoder_kernel(const float* __restrict__ query,
                               const float* __restrict__ key_,
                               const float* __restrict__ Wqe, const float* __restrict__ bqe,
                               const float* __restrict__ Wke, const float* __restrict__ bke)
{
    float* S = g_scratch;
    int y = blockIdx.y;
    if (y < 16)
        gemm_tile(query, Wqe, bqe, S + OFF_QF, Ed, 1, y * 32, blockIdx.x * 64);
    else
        gemm_tile(key_,  Wke, bke, S + OFF_KF, Ed, 1, (y - 16) * 32, blockIdx.x * 64);
}

// Launch 2: 4 projections (b0 folded into qp, bv1 into qv) + W transpose (fp16).
// grid (4, 32, 5)
__global__ void proj_trans_kernel(const float* __restrict__ W0,
                                  const float* __restrict__ Wv1,
                                  const float* __restrict__ W1,
                                  const float* __restrict__ W2,
                                  const float* __restrict__ b0,
                                  const float* __restrict__ bv1)
{
    float* S = g_scratch;
    const int z = blockIdx.z;
    if (z < 4) {
        const float* A; const float* W; float* C; const float* bias;
        switch (z) {
            case 0: A = S + OFF_QF; W = W0;            C = S + OFF_QP; bias = b0;     break;
            case 1: A = S + OFF_KF; W = W0 + Hd * Hd;  C = S + OFF_KP; bias = nullptr;break;
            case 2: A = S + OFF_QF; W = Wv1;           C = S + OFF_QV; bias = bv1;    break;
            default:A = S + OFF_KF; W = Wv1 + Hd * Hd; C = S + OFF_KV; bias = nullptr;break;
        }
        int M = (z == 1 || z == 3) ? 1024 : 512;
        if (blockIdx.y * 32 >= M) return;
        gemm_tile(A, W, bias, C, Hd, 0, blockIdx.y * 32, blockIdx.x * 64);
    } else {
        // transpose + fp16 round of W1, W2 into g_wt (Wt[n][k] row-major)
        int lin = blockIdx.y * 4 + blockIdx.x;      // 0..127
        const float* W = (lin >= 64) ? W2 : W1;
        __half* oh = g_wt + (size_t)(lin >= 64 ? 1 : 0) * 65536;
        int base = (lin & 63) * 1024;
        #pragma unroll
        for (int t = 0; t < 4; t++) {
            int e = base + t * 256 + threadIdx.x;
            int n = e >> 8, k = e & 255;
            oh[e] = __float2half_rn(__ldg(W + (size_t)k * 256 + n));
        }
    }
}

// ---------------------------------------------------------------------------
// HMMA fused pair kernel: single-term fp16 GEMM, K=64 chunks, register
// double-buffered fragments (software pipeline).
// CTA = (b, q, 128 k-pairs). M=128, N=256, K=256. 256 threads, 8 warps 2Mx4N.
// ---------------------------------------------------------------------------
#define APITCH 264                       // fp16 elems per A row (528 B)
#define SM_AH 0
#define SM_W  (128 * APITCH * 2)         // 67584
#define WPITCH 144                       // bytes per W chunk row (64 fp16 + pad)
#define WBUF_BYTES (256 * WPITCH)        // 36864
#define SM_PART (SM_W + 2 * WBUF_BYTES)  // 141312
#define SMEM_TOTAL (SM_PART + 512 * 4)   // 143360

// load one k16-step of fragments (A rows + B cols) for this warp
__device__ __forceinline__ void load_step(uint32_t sbase, uint32_t wbuf,
                                          uint32_t a_rowoff, uint32_t b_rowoff,
                                          int kc, int ks,
                                          uint32_t afh[4][4], uint32_t bh[8][2])
{
    const uint32_t a_k = (uint32_t)(kc * 64 + ks * 16) * 2;
    const uint32_t b_k = (uint32_t)ks * 32;
    #pragma unroll
    for (int mi = 0; mi < 4; mi++)
        ldsm4(afh[mi], sbase + SM_AH + a_rowoff + (uint32_t)mi * 16 * (APITCH * 2) + a_k);
    #pragma unroll
    for (int np = 0; np < 4; np++) {
        uint32_t r[4];
        ldsm4(r, wbuf + b_rowoff + (uint32_t)np * 16 * WPITCH + b_k);
        bh[2*np][0] = r[0]; bh[2*np][1] = r[1];
        bh[2*np+1][0] = r[2]; bh[2*np+1][1] = r[3];
    }
}

__global__ void __launch_bounds__(256, 1)
pair_mma_kernel(const float* __restrict__ b1, const float* __restrict__ b2,
                const float* __restrict__ Wf, const float* __restrict__ bf,
                const float* __restrict__ Wv2, const float* __restrict__ bv2,
                float* __restrict__ out)
{
    extern __shared__ char smem[];
    const uint32_t sbase = smem_to_u32(smem);

    const int tid = threadIdx.x;
    const int w   = tid >> 5;
    const int wm  = w >> 2;            // 0..1 : M group (64 rows)
    const int wn  = w & 3;             // 0..3 : N group (64 cols)
    const int lt  = tid & 31;
    const int lrow = lt >> 2;          // 0..7
    const int lc2  = (lt & 3) * 2;     // 0,2,4,6

    // ldmatrix per-lane row offsets
    const uint32_t a_rowoff = (uint32_t)(wm * 64 + (lt & 15)) * (APITCH * 2)
                            + (uint32_t)((lt >> 4) * 8) * 2;
    const uint32_t b_rowoff = (uint32_t)(wn * 64 + (lt & 7) + ((lt >> 4) & 1) * 8) * WPITCH
                            + (uint32_t)((lt >> 3) & 1) * 16;

    const int kb = blockIdx.x, q = blockIdx.y, b = blockIdx.z;
    const int qrow  = b * SQd + q;
    const int krow0 = b * SKd + kb * 128;

    const float* qp = g_scratch + OFF_QP + (size_t)qrow  * Hd;   // b0 pre-folded
    const float* kp = g_scratch + OFF_KP + (size_t)krow0 * Hd;
    const float* qv = g_scratch + OFF_QV + (size_t)qrow  * Hd;   // bv1 pre-folded
    const float* kv = g_scratch + OFF_KV + (size_t)krow0 * Hd;

    // ---- prefetch W chunk 0 (layer 0) via cp.async: 256 rows x 128 B
    {
        #pragma unroll
        for (int it = 0; it < 8; it++) {
            int u = tid + it * 256;             // 0..2047
            int n = u >> 3, j = u & 7;
            cp16(sbase + SM_W + n * WPITCH + j * 16, g_wt + n * 256 + j * 8);
        }
        CP_COMMIT();
    }

    // ---- variance branch: v = relu(qv'+kv); softplus(v.Wv2 + bv2)
    {
        const int r = tid >> 1, part = tid & 1;
        const float* qvr = qv + part * 128;
        const float* kvr = kv + (size_t)r * Hd + part * 128;
        const float* wvr = Wv2 + part * 128;
        float s = 0.f;
        #pragma unroll
        for (int i = 0; i < 32; i++) {
            float4 a = ldg4(qvr + i * 4);
            float4 c = ldg4(kvr + i * 4);
            float4 ww = ldg4(wvr + i * 4);
            s = fmaf(frelu(a.x + c.x), ww.x, s);
            s = fmaf(frelu(a.y + c.y), ww.y, s);
            s = fmaf(frelu(a.z + c.z), ww.z, s);
            s = fmaf(frelu(a.w + c.w), ww.w, s);
        }
        s += __shfl_down_sync(0xffffffffu, s, 1);
        if (part == 0) {
            float x = s + __ldg(bv2);
            out[(size_t)Bsz * SQd * SKd + (size_t)qrow * SKd + kb * 128 + r] =
                fmaxf(x, 0.f) + log1pf(expf(-fabsf(x)));
        }
    }

    // ---- build A = relu(qp' + kp) -> fp16 -> SMEM
    {
        const int row = tid >> 1, half = (tid & 1) * 128;
        const float* qpr = qp + half;
        const float* kpr = kp + (size_t)row * Hd + half;
        #pragma unroll
        for (int j4 = 0; j4 < 32; j4++) {
            float4 a  = ldg4(qpr + j4 * 4);
            float4 c  = ldg4(kpr + j4 * 4);
            uint32_t h0 = pack2h(frelu(a.x + c.x), frelu(a.y + c.y));
            uint32_t h1 = pack2h(frelu(a.z + c.z), frelu(a.w + c.w));
            uint32_t off = (uint32_t)row * (APITCH * 2) + (half + j4 * 4) * 2;
            *(uint2*)(smem + SM_AH + off) = make_uint2(h0, h1);
        }
    }
    CP_WAIT0();
    __syncthreads();

    // ---- accumulators: fp32 c[4][8][4]; fragments double-buffered
    float c[4][8][4];
    uint32_t afh[2][4][4], bh[2][8][2];
    #pragma unroll
    for (int mi = 0; mi < 4; mi++)
        #pragma unroll
        for (int ni = 0; ni < 8; ni++)
            #pragma unroll
            for (int jj = 0; jj < 4; jj++) c[mi][ni][jj] = 0.f;

    // ---- 2 layers x 4 chunks of K=64; double-buffered cp.async + reg pipeline
    #pragma unroll 1
    for (int layer = 0; layer < 2; layer++) {
        #pragma unroll 1
        for (int kc = 0; kc < 4; kc++) {
            const int gg = layer * 4 + kc;
            const uint32_t wbuf = sbase + SM_W + (uint32_t)(gg & 1) * WBUF_BYTES;

            // load step-0 fragments first (starts the ldsm chain ASAP)
            load_step(sbase, wbuf, a_rowoff, b_rowoff, kc, 0, afh[0], bh[0]);

            // prefetch next chunk
            if (gg + 1 < 8) {
                const __half* Wh = g_wt + (size_t)((gg + 1) >> 2) * 65536;
                const int nkc = (gg + 1) & 3;
                const uint32_t dbase = sbase + SM_W + ((gg + 1) & 1) * WBUF_BYTES;
                #pragma unroll
                for (int it = 0; it < 8; it++) {
                    int u = tid + it * 256;
                    int n = u >> 3, j = u & 7;
                    cp16(dbase + n * WPITCH + j * 16, Wh + n * 256 + nkc * 64 + j * 8);
                }
                CP_COMMIT();
            }

            // pipelined compute: load ks+1 before mma of ks
            #pragma unroll
            for (int ks = 0; ks < 4; ks++) {
                if (ks < 3)
                    load_step(sbase, wbuf, a_rowoff, b_rowoff, kc, ks + 1,
                              afh[(ks + 1) & 1], bh[(ks + 1) & 1]);
                #pragma unroll
                for (int mi = 0; mi < 4; mi++)
                    #pragma unroll
                    for (int ni = 0; ni < 8; ni++)
                        mma_f32acc(c[mi][ni], afh[ks & 1][mi], bh[ks & 1][ni]);
            }

            CP_WAIT0();
            __syncthreads();
        }

        // ---- between layers: h1 = relu(D + b1) -> fp16 -> A SMEM; reset accum
        if (layer == 0) {
            #pragma unroll
            for (int ni = 0; ni < 8; ni++) {
                int n = wn * 64 + ni * 8 + lc2;
                float2 bb = *(const float2*)(b1 + n);
                #pragma unroll
                for (int mi = 0; mi < 4; mi++) {
                    int m1 = wm * 64 + mi * 16 + lrow;
                    uint32_t off1 = (uint32_t)m1 * (APITCH * 2) + n * 2;
                    *(uint32_t*)(smem + SM_AH + off1) =
                        pack2h(frelu(c[mi][ni][0] + bb.x), frelu(c[mi][ni][1] + bb.y));
                    uint32_t off2 = off1 + 8 * (APITCH * 2);
                    *(uint32_t*)(smem + SM_AH + off2) =
                        pack2h(frelu(c[mi][ni][2] + bb.x), frelu(c[mi][ni][3] + bb.y));
                    c[mi][ni][0] = 0.f; c[mi][ni][1] = 0.f;
                    c[mi][ni][2] = 0.f; c[mi][ni][3] = 0.f;
                }
            }
            __syncthreads();
        }
    }

    // ---- final epilogue: logit = relu(D + b2) . Wf + bf
    float* part = (float*)(smem + SM_PART);
    float ps1[4], ps2[4];
    #pragma unroll
    for (int mi = 0; mi < 4; mi++) { ps1[mi] = 0.f; ps2[mi] = 0.f; }
    #pragma unroll
    for (int ni = 0; ni < 8; ni++) {
        int n = wn * 64 + ni * 8 + lc2;
        float2 bb = *(const float2*)(b2 + n);
        float2 wf = *(const float2*)(Wf + n);
        #pragma unroll
        for (int mi = 0; mi < 4; mi++) {
            ps1[mi] = fmaf(frelu(c[mi][ni][0] + bb.x), wf.x, ps1[mi]);
            ps1[mi] = fmaf(frelu(c[mi][ni][1] + bb.y), wf.y, ps1[mi]);
            ps2[mi] = fmaf(frelu(c[mi][ni][2] + bb.x), wf.x, ps2[mi]);
            ps2[mi] = fmaf(frelu(c[mi][ni][3] + bb.y), wf.y, ps2[mi]);
        }
    }
    #pragma unroll
    for (int mi = 0; mi < 4; mi++) {
        ps1[mi] += __shfl_xor_sync(0xffffffffu, ps1[mi], 1);
        ps1[mi] += __shfl_xor_sync(0xffffffffu, ps1[mi], 2);
        ps2[mi] += __shfl_xor_sync(0xffffffffu, ps2[mi], 1);
        ps2[mi] += __shfl_xor_sync(0xffffffffu, ps2[mi], 2);
    }
    if ((lt & 3) == 0) {
        #pragma unroll
        for (int mi = 0; mi < 4; mi++) {
            int m1 = wm * 64 + mi * 16 + lrow;
            part[wn * 128 + m1]     = ps1[mi];
            part[wn * 128 + m1 + 8] = ps2[mi];
        }
    }
    __syncthreads();
    if (tid < 128) {
        float s = part[tid] + part[128 + tid] + part[256 + tid] + part[384 + tid]
                + __ldg(bf);
        out[(size_t)qrow * SKd + kb * 128 + tid] = s;
    }
}

// ---------------------------------------------------------------------------
// Launch (3 launches per call)
// ---------------------------------------------------------------------------
extern "C" void kernel_launch(void* const* d_in, const int* in_sizes, int n_in,
                              void* d_out, int out_size)
{
    (void)in_sizes; (void)n_in; (void)out_size;
    const float* query = (const float*)d_in[0];
    const float* key_  = (const float*)d_in[1];
    const float* Wqe   = (const float*)d_in[2];
    const float* bqe   = (const float*)d_in[3];
    const float* Wke   = (const float*)d_in[4];
    const float* bke   = (const float*)d_in[5];
    const float* W0    = (const float*)d_in[6];
    const float* b0    = (const float*)d_in[7];
    const float* W1    = (const float*)d_in[8];
    const float* b1    = (const float*)d_in[9];
    const float* W2    = (const float*)d_in[10];
    const float* b2    = (const float*)d_in[11];
    const float* Wf    = (const float*)d_in[12];
    const float* bf    = (const float*)d_in[13];
    const float* Wv1   = (const float*)d_in[14];
    const float* bv1   = (const float*)d_in[15];
    const float* Wv2   = (const float*)d_in[16];
    const float* bv2   = (const float*)d_in[17];
    float* out = (float*)d_out;

    cudaFuncSetAttribute(pair_mma_kernel,
                         cudaFuncAttributeMaxDynamicSharedMemorySize, SMEM_TOTAL);

    // 1: encoders (qf, kf)
    encoder_kernel<<<dim3(4, 48), 256>>>(query, key_, Wqe, bqe, Wke, bke);
    // 2: projections (qp+b0, kp, qv+bv1, kv) + W1/W2 transpose (fp16)
    proj_trans_kernel<<<dim3(4, 32, 5), 256>>>(W0, Wv1, W1, W2, b0, bv1);
    // 3: fused HMMA pair MLP (single-term fp16, K=64 chunks, reg pipeline)
    pair_mma_kernel<<<dim3(SKd / 128, SQd, Bsz), 256, SMEM_TOTAL>>>(
        b1, b2, Wf, bf, Wv2, bv2, out);
}